// round 11
// baseline (speedup 1.0000x reference)
#include <cuda_runtime.h>
#include <math.h>
#include <float.h>

#define Bb   512
#define Cc   2048
#define HWn  48
#define NAT  51
#define HIDn 128
#define S1   16    // K-splits for pooled @ W1^T  (K=2048 -> 128/split)
#define NTIL 32    // channel tiles in gate kernel (2048/64)

// Scratch (static __device__ globals: allocation-free rule)
__device__ float g_pooled[Bb * Cc];            // max_hw(body*A*face), 0 for non-front rows
__device__ float g_bmean [Bb * Cc];            // mean_hw(body)
__device__ float g_hp    [S1 * Bb * HIDn];     // split-K partials of pooled @ W1^T
__device__ float g_h     [Bb * HIDn];          // relu(sum hp + b1)
__device__ float g_zp    [NTIL * NAT * Bb];    // per-n-tile partials of gap @ Wl^T, [nt][j][b]
__device__ float g_WlT   [Cc * 64];            // Wl transposed+padded: [c][j], j>=51 zero

// ---------------------------------------------------------------------------
// WLT: one-time transpose of Wl [51][2048] -> g_WlT [2048][64] (pad zeros).
// Block: 64 channels. Read coalesced along c, bounce via smem, write coalesced.
// ---------------------------------------------------------------------------
__global__ void __launch_bounds__(256) wl_transpose(const float* __restrict__ Wl)
{
    __shared__ float sm[64][52];          // [c][j], 52 to de-conflict
    int c0 = blockIdx.x * 64;
    int tid = threadIdx.x;
    for (int idx = tid; idx < NAT * 64; idx += 256) {
        int j = idx >> 6, c = idx & 63;
        sm[c][j] = Wl[(size_t)j * Cc + c0 + c];
    }
    __syncthreads();
    for (int idx = tid; idx < 64 * 64; idx += 256) {
        int c = idx >> 6, j = idx & 63;
        g_WlT[(size_t)(c0 + c) * 64 + j] = (j < NAT) ? sm[c][j] : 0.f;
    }
}

// ---------------------------------------------------------------------------
// K1 v3: streaming pass, float4 loads, 16 channels/warp (6 independent body
// LDG.128 in flight), 128 channels/block. Reduction: 2 threads/channel + 1 shfl.
// ---------------------------------------------------------------------------
__global__ void __launch_bounds__(256) k1_reduce(
    const float* __restrict__ body, const float* __restrict__ face,
    const float* __restrict__ Af,   const int*   __restrict__ pose)
{
    __shared__ float sm_s[8][192];
    __shared__ float sm_m[8][192];
    __shared__ float out_s[128], out_m[128];
    int tid  = threadIdx.x;
    int wid  = tid >> 5;
    int lane = tid & 31;
    int blk_ch = blockIdx.x * 128;         // 128 channels of ONE b (16 blocks per b)
    int b = blk_ch >> 11;
    bool front = (pose[b] == 1);
    int wbase = blk_ch + wid * 16;         // this warp's first channel

    const float4* bp4 = (const float4*)body + (size_t)wbase * 12;
    float4 bv[6];
    #pragma unroll
    for (int k = 0; k < 6; k++)
        bv[k] = bp4[k * 32 + lane];
    if (front) {
        const float4* fp4 = (const float4*)face + (size_t)wbase * 12;
        const float4* ap4 = (const float4*)Af   + (size_t)(wbase & (Cc - 1)) * 12;
        #pragma unroll
        for (int k = 0; k < 6; k++) {
            float4 fv = fp4[k * 32 + lane];
            float4 av = ap4[k * 32 + lane];
            float m01 = fmaxf(bv[k].x * av.x * fv.x, bv[k].y * av.y * fv.y);
            float m23 = fmaxf(bv[k].z * av.z * fv.z, bv[k].w * av.w * fv.w);
            sm_m[wid][k * 32 + lane] = fmaxf(m01, m23);
        }
    }
    #pragma unroll
    for (int k = 0; k < 6; k++)
        sm_s[wid][k * 32 + lane] = (bv[k].x + bv[k].y) + (bv[k].z + bv[k].w);
    __syncthreads();

    // Phase 2: 2 threads per channel, 6 partials each, then 1 shfl level.
    {
        int chl = tid >> 1;                // 0..127 local channel
        int w2  = chl >> 4;                // source warp
        int off = (chl & 15) * 12 + (tid & 1) * 6;
        float ss = 0.f;
        #pragma unroll
        for (int i = 0; i < 6; i++) ss += sm_s[w2][off + i];
        ss += __shfl_xor_sync(0xffffffffu, ss, 1);
        float mm = 0.f;
        if (front) {
            mm = -FLT_MAX;
            #pragma unroll
            for (int i = 0; i < 6; i++) mm = fmaxf(mm, sm_m[w2][off + i]);
            mm = fmaxf(mm, __shfl_xor_sync(0xffffffffu, mm, 1));
        }
        if ((tid & 1) == 0) {
            out_s[chl] = ss * (1.0f / 48.0f);
            out_m[chl] = mm;
        }
    }
    __syncthreads();
    if (tid < 128)  g_bmean [blk_ch + tid]       = out_s[tid];
    else            g_pooled[blk_ch + tid - 128] = out_m[tid - 128];
}

// ---------------------------------------------------------------------------
// GEMM1 split-K: hp[s] = pooled[512, k-chunk] @ W1[128, k-chunk]^T (unchanged)
// ---------------------------------------------------------------------------
__global__ void __launch_bounds__(256) gemm1(
    const float* __restrict__ A, const float* __restrict__ Bw,
    float* __restrict__ hp)
{
    __shared__ float As[16][68];
    __shared__ float Bs[16][68];
    int s  = blockIdx.z;
    int m0 = blockIdx.x * 64;
    int n0 = blockIdx.y * 64;
    int k0 = s * (Cc / S1);
    int tid = threadIdx.x;
    int tx = tid & 15, ty = tid >> 4;
    int r  = tid >> 2;
    int q  = (tid & 3) * 4;
    float acc[4][4] = {};

    const float* ap = &A [(size_t)(m0 + r) * Cc + k0 + q];
    const float* bp = &Bw[(size_t)(n0 + r) * Cc + k0 + q];
    float4 areg = *(const float4*)ap;
    float4 breg = *(const float4*)bp;

    #pragma unroll
    for (int kt = 0; kt < Cc / S1; kt += 16) {
        As[q+0][r] = areg.x; As[q+1][r] = areg.y; As[q+2][r] = areg.z; As[q+3][r] = areg.w;
        Bs[q+0][r] = breg.x; Bs[q+1][r] = breg.y; Bs[q+2][r] = breg.z; Bs[q+3][r] = breg.w;
        __syncthreads();
        if (kt + 16 < Cc / S1) {
            areg = *(const float4*)(ap + kt + 16);
            breg = *(const float4*)(bp + kt + 16);
        }
        #pragma unroll
        for (int kk = 0; kk < 16; kk++) {
            float4 a4 = *(const float4*)&As[kk][ty * 4];
            float4 b4 = *(const float4*)&Bs[kk][tx * 4];
            float a[4]  = {a4.x, a4.y, a4.z, a4.w};
            float bb[4] = {b4.x, b4.y, b4.z, b4.w};
            #pragma unroll
            for (int i = 0; i < 4; i++)
                #pragma unroll
                for (int j = 0; j < 4; j++)
                    acc[i][j] = fmaf(a[i], bb[j], acc[i][j]);
        }
        __syncthreads();
    }
    #pragma unroll
    for (int i = 0; i < 4; i++) {
        int m = m0 + ty * 4 + i;
        #pragma unroll
        for (int j = 0; j < 4; j++) {
            int n = n0 + tx * 4 + j;
            hp[((size_t)s * Bb + m) * HIDn + n] = acc[i][j];
        }
    }
}

// ---------------------------------------------------------------------------
// hreduce: 256 blocks, scalar per thread (proven).
// ---------------------------------------------------------------------------
__global__ void __launch_bounds__(256) hreduce(const float* __restrict__ b1v)
{
    int i = blockIdx.x * 256 + threadIdx.x;
    float v = g_hp[i];
    #pragma unroll
    for (int s = 1; s < S1; s++)
        v += g_hp[(size_t)s * (Bb * HIDn) + i];
    v += b1v[i & (HIDn - 1)];
    g_h[i] = fmaxf(v, 0.f);
}

// ---------------------------------------------------------------------------
// GATE (R3 skeleton, fastest measured) with coalesced WlT fill from g_WlT.
// ---------------------------------------------------------------------------
__global__ void __launch_bounds__(256) gemm_gate(
    const float* __restrict__ W2,  const float* __restrict__ b2v,
    const int*   __restrict__ pose)
{
    __shared__ __align__(16) float smemBuf[64 * 68 + 64 * 68];   // 34816 B
    float (*As)[68]   = (float(*)[68]) smemBuf;                  // [16][68]
    float (*Bs)[68]   = (float(*)[68])(smemBuf + 16 * 68);       // [16][68]
    float (*gapT)[68] = (float(*)[68]) smemBuf;                  // [64][68]
    float (*WlT)[68]  = (float(*)[68])(smemBuf + 64 * 68);       // [64][68]

    int m0 = blockIdx.x * 64;
    int n0 = blockIdx.y * 64;
    int tid = threadIdx.x;
    int tx = tid & 15, ty = tid >> 4;
    int r  = tid >> 2;
    int q  = (tid & 3) * 4;
    float acc[4][4] = {};

    const float* ap = &g_h[(size_t)(m0 + r) * HIDn + q];
    const float* bp = &W2 [(size_t)(n0 + r) * HIDn + q];
    float4 areg = *(const float4*)ap;
    float4 breg = *(const float4*)bp;

    #pragma unroll
    for (int kt = 0; kt < HIDn; kt += 16) {
        As[q+0][r] = areg.x; As[q+1][r] = areg.y; As[q+2][r] = areg.z; As[q+3][r] = areg.w;
        Bs[q+0][r] = breg.x; Bs[q+1][r] = breg.y; Bs[q+2][r] = breg.z; Bs[q+3][r] = breg.w;
        __syncthreads();
        if (kt + 16 < HIDn) {
            areg = *(const float4*)(ap + kt + 16);
            breg = *(const float4*)(bp + kt + 16);
        }
        #pragma unroll
        for (int kk = 0; kk < 16; kk++) {
            float4 a4 = *(const float4*)&As[kk][ty * 4];
            float4 b4 = *(const float4*)&Bs[kk][tx * 4];
            float a[4]  = {a4.x, a4.y, a4.z, a4.w};
            float bb[4] = {b4.x, b4.y, b4.z, b4.w};
            #pragma unroll
            for (int i = 0; i < 4; i++)
                #pragma unroll
                for (int j = 0; j < 4; j++)
                    acc[i][j] = fmaf(a[i], bb[j], acc[i][j]);
        }
        __syncthreads();
    }

    // --- epilogue: gap values -> gapT (chan-major).
    #pragma unroll
    for (int i = 0; i < 4; i++) {
        int m = m0 + ty * 4 + i;
        float fr = (pose[m] == 1) ? 1.0f : 0.0f;
        #pragma unroll
        for (int j = 0; j < 4; j++) {
            int n = n0 + tx * 4 + j;
            float v = acc[i][j] + b2v[n];
            float g = 1.0f / (1.0f + expf(-v));
            gapT[tx * 4 + j][ty * 4 + i] =
                g_bmean[(size_t)m * Cc + n] + fr * g;
        }
    }
    // WlT fill: coalesced float4 rows from pre-transposed g_WlT (pad j 64..67).
    for (int idx4 = tid; idx4 < 64 * 17; idx4 += 256) {
        int cc = idx4 / 17, qq = idx4 - cc * 17;
        float4 v = (qq < 16)
            ? ((const float4*)&g_WlT[(size_t)(n0 + cc) * 64])[qq]
            : make_float4(0.f, 0.f, 0.f, 0.f);
        *(float4*)&WlT[cc][qq * 4] = v;
    }
    __syncthreads();

    // mini-GEMM: zpart[row, attr] = sum_cc gapT[cc][row] * WlT[cc][attr]
    float acc2[4][4] = {};
    #pragma unroll 8
    for (int cc = 0; cc < 64; cc++) {
        float4 g4 = *(const float4*)&gapT[cc][ty * 4];
        float4 w4 = *(const float4*)&WlT [cc][tx * 4];
        float gg[4] = {g4.x, g4.y, g4.z, g4.w};
        float ww[4] = {w4.x, w4.y, w4.z, w4.w};
        #pragma unroll
        for (int i = 0; i < 4; i++)
            #pragma unroll
            for (int j = 0; j < 4; j++)
                acc2[i][j] = fmaf(gg[i], ww[j], acc2[i][j]);
    }
    int nt = blockIdx.y;
    #pragma unroll
    for (int j = 0; j < 4; j++) {
        int attr = tx * 4 + j;
        if (attr < NAT) {
            #pragma unroll
            for (int i = 0; i < 4; i++) {
                int m = m0 + ty * 4 + i;
                g_zp[((size_t)nt * NAT + attr) * Bb + m] = acc2[i][j];
            }
        }
    }
}

// ---------------------------------------------------------------------------
// BN: one block per attribute (NTIL=32 partials).
// ---------------------------------------------------------------------------
__global__ void __launch_bounds__(256) bn_kernel(
    const float* __restrict__ blv, const float* __restrict__ gam,
    const float* __restrict__ bet, float* __restrict__ out)
{
    __shared__ float zbuf[Bb];
    __shared__ float red[256];
    int j   = blockIdx.x;
    int tid = threadIdx.x;
    float bias = blv[j];
    float lsum = 0.f;
    for (int b = tid; b < Bb; b += 256) {
        float z = bias;
        #pragma unroll
        for (int nt = 0; nt < NTIL; nt++)
            z += g_zp[((size_t)nt * NAT + j) * Bb + b];
        zbuf[b] = z;
        lsum += z;
    }
    red[tid] = lsum;
    __syncthreads();
    for (int off = 128; off; off >>= 1) {
        if (tid < off) red[tid] += red[tid + off];
        __syncthreads();
    }
    float mu = red[0] * (1.0f / Bb);
    __syncthreads();
    float lvar = 0.f;
    for (int b = tid; b < Bb; b += 256) {
        float d = zbuf[b] - mu;
        lvar += d * d;
    }
    red[tid] = lvar;
    __syncthreads();
    for (int off = 128; off; off >>= 1) {
        if (tid < off) red[tid] += red[tid + off];
        __syncthreads();
    }
    float inv = rsqrtf(red[0] * (1.0f / Bb) + 1e-5f);
    float ga = gam[j], be = bet[j];
    for (int b = tid; b < Bb; b += 256)
        out[(size_t)b * NAT + j] = ga * (zbuf[b] - mu) * inv + be;
}

// ---------------------------------------------------------------------------
extern "C" void kernel_launch(void* const* d_in, const int* in_sizes, int n_in,
                              void* d_out, int out_size)
{
    const float* body = (const float*)d_in[0];
    const float* face = (const float*)d_in[1];
    const int*   pose = (const int*)  d_in[2];
    const float* Af   = (const float*)d_in[3];
    const float* W1   = (const float*)d_in[4];
    const float* b1v  = (const float*)d_in[5];
    const float* W2   = (const float*)d_in[6];
    const float* b2v  = (const float*)d_in[7];
    const float* Wl   = (const float*)d_in[8];
    const float* blv  = (const float*)d_in[9];
    const float* gam  = (const float*)d_in[10];
    const float* bet  = (const float*)d_in[11];
    float* out = (float*)d_out;

    float *pooled_p, *hp_p;
    cudaGetSymbolAddress((void**)&pooled_p, g_pooled);
    cudaGetSymbolAddress((void**)&hp_p,     g_hp);

    // 0) one-time Wl transpose (tiny; removes epilogue gather)
    wl_transpose<<<Cc / 64, 256>>>(Wl);
    // 1) streaming reduce: pooled max + body mean (128 channels/block)
    k1_reduce<<<(Bb * Cc) / 128, 256>>>(body, face, Af, pose);
    // 2) hp[s] = pooled @ W1^T  (16-way split-K partials)
    gemm1<<<dim3(Bb / 64, HIDn / 64, S1), 256>>>(pooled_p, W1, hp_p);
    // 3) h = relu(sum hp + b1)
    hreduce<<<(Bb * HIDn) / 256, 256>>>(b1v);
    // 4) gate GEMM (R3 config) + fused z-partial epilogue (coalesced WlT)
    gemm_gate<<<dim3(Bb / 64, NTIL), 256>>>(W2, b2v, pose);
    // 5) reduce partials + bias + batchnorm
    bn_kernel<<<NAT, 256>>>(blv, gam, bet, out);
}

// round 12
// speedup vs baseline: 1.0885x; 1.0885x over previous
#include <cuda_runtime.h>
#include <math.h>
#include <float.h>

#define Bb   512
#define Cc   2048
#define HWn  48
#define NAT  51
#define HIDn 128
#define S1   16    // K-splits for pooled @ W1^T  (K=2048 -> 128/split)
#define NTIL 32    // channel tiles in gate kernel (2048/64)

// Scratch (static __device__ globals: allocation-free rule)
__device__ float g_pooled[Bb * Cc];            // max_hw(body*A*face), 0 for non-front rows
__device__ float g_bmean [Bb * Cc];            // mean_hw(body)
__device__ float g_hp    [S1 * Bb * HIDn];     // split-K partials of pooled @ W1^T
__device__ float g_h     [Bb * HIDn];          // relu(sum hp + b1)
__device__ float g_zp    [NTIL * NAT * Bb];    // per-n-tile partials of gap @ Wl^T, [nt][j][b]

// ---------------------------------------------------------------------------
// K1: streaming pass, float4 loads (R5/R10 version — proven, near HBM bound).
// ---------------------------------------------------------------------------
__global__ void __launch_bounds__(256) k1_reduce(
    const float* __restrict__ body, const float* __restrict__ face,
    const float* __restrict__ Af,   const int*   __restrict__ pose)
{
    __shared__ float sm_s[8][96];
    __shared__ float sm_m[8][96];
    __shared__ float out_s[64], out_m[64];
    int tid  = threadIdx.x;
    int wid  = tid >> 5;
    int lane = tid & 31;
    int blk_ch = blockIdx.x * 64;
    int b = blk_ch >> 11;
    bool front = (pose[b] == 1);
    int wbase = blk_ch + wid * 8;

    const float4* bp4 = (const float4*)body + (size_t)wbase * 12;
    float4 bv[3];
    #pragma unroll
    for (int k = 0; k < 3; k++)
        bv[k] = bp4[k * 32 + lane];
    if (front) {
        const float4* fp4 = (const float4*)face + (size_t)wbase * 12;
        const float4* ap4 = (const float4*)Af   + (size_t)(wbase & (Cc - 1)) * 12;
        #pragma unroll
        for (int k = 0; k < 3; k++) {
            float4 fv = fp4[k * 32 + lane];
            float4 av = ap4[k * 32 + lane];
            float m01 = fmaxf(bv[k].x * av.x * fv.x, bv[k].y * av.y * fv.y);
            float m23 = fmaxf(bv[k].z * av.z * fv.z, bv[k].w * av.w * fv.w);
            sm_m[wid][k * 32 + lane] = fmaxf(m01, m23);
        }
    }
    #pragma unroll
    for (int k = 0; k < 3; k++)
        sm_s[wid][k * 32 + lane] = (bv[k].x + bv[k].y) + (bv[k].z + bv[k].w);
    __syncthreads();

    {
        int chl = tid >> 2;
        int w2  = chl >> 3;
        int off = (chl & 7) * 12 + (tid & 3) * 3;
        float ss = sm_s[w2][off] + sm_s[w2][off + 1] + sm_s[w2][off + 2];
        ss += __shfl_xor_sync(0xffffffffu, ss, 1);
        ss += __shfl_xor_sync(0xffffffffu, ss, 2);
        float mm = 0.f;
        if (front) {
            mm = fmaxf(fmaxf(sm_m[w2][off], sm_m[w2][off + 1]), sm_m[w2][off + 2]);
            mm = fmaxf(mm, __shfl_xor_sync(0xffffffffu, mm, 1));
            mm = fmaxf(mm, __shfl_xor_sync(0xffffffffu, mm, 2));
        }
        if ((tid & 3) == 0) {
            out_s[chl] = ss * (1.0f / 48.0f);
            out_m[chl] = mm;
        }
    }
    __syncthreads();
    if (tid < 64)        g_bmean [blk_ch + tid]      = out_s[tid];
    else if (tid < 128)  g_pooled[blk_ch + tid - 64] = out_m[tid - 64];
}

// ---------------------------------------------------------------------------
// GEMM1 split-K: hp[s] = pooled[512, k-chunk] @ W1[128, k-chunk]^T (unchanged)
// ---------------------------------------------------------------------------
__global__ void __launch_bounds__(256) gemm1(
    const float* __restrict__ A, const float* __restrict__ Bw,
    float* __restrict__ hp)
{
    __shared__ float As[16][68];
    __shared__ float Bs[16][68];
    int s  = blockIdx.z;
    int m0 = blockIdx.x * 64;
    int n0 = blockIdx.y * 64;
    int k0 = s * (Cc / S1);
    int tid = threadIdx.x;
    int tx = tid & 15, ty = tid >> 4;
    int r  = tid >> 2;
    int q  = (tid & 3) * 4;
    float acc[4][4] = {};

    const float* ap = &A [(size_t)(m0 + r) * Cc + k0 + q];
    const float* bp = &Bw[(size_t)(n0 + r) * Cc + k0 + q];
    float4 areg = *(const float4*)ap;
    float4 breg = *(const float4*)bp;

    #pragma unroll
    for (int kt = 0; kt < Cc / S1; kt += 16) {
        As[q+0][r] = areg.x; As[q+1][r] = areg.y; As[q+2][r] = areg.z; As[q+3][r] = areg.w;
        Bs[q+0][r] = breg.x; Bs[q+1][r] = breg.y; Bs[q+2][r] = breg.z; Bs[q+3][r] = breg.w;
        __syncthreads();
        if (kt + 16 < Cc / S1) {
            areg = *(const float4*)(ap + kt + 16);
            breg = *(const float4*)(bp + kt + 16);
        }
        #pragma unroll
        for (int kk = 0; kk < 16; kk++) {
            float4 a4 = *(const float4*)&As[kk][ty * 4];
            float4 b4 = *(const float4*)&Bs[kk][tx * 4];
            float a[4]  = {a4.x, a4.y, a4.z, a4.w};
            float bb[4] = {b4.x, b4.y, b4.z, b4.w};
            #pragma unroll
            for (int i = 0; i < 4; i++)
                #pragma unroll
                for (int j = 0; j < 4; j++)
                    acc[i][j] = fmaf(a[i], bb[j], acc[i][j]);
        }
        __syncthreads();
    }
    #pragma unroll
    for (int i = 0; i < 4; i++) {
        int m = m0 + ty * 4 + i;
        #pragma unroll
        for (int j = 0; j < 4; j++) {
            int n = n0 + tx * 4 + j;
            hp[((size_t)s * Bb + m) * HIDn + n] = acc[i][j];
        }
    }
}

// ---------------------------------------------------------------------------
// hreduce: 256 blocks, scalar per thread (proven).
// ---------------------------------------------------------------------------
__global__ void __launch_bounds__(256) hreduce(const float* __restrict__ b1v)
{
    int i = blockIdx.x * 256 + threadIdx.x;
    float v = g_hp[i];
    #pragma unroll
    for (int s = 1; s < S1; s++)
        v += g_hp[(size_t)s * (Bb * HIDn) + i];
    v += b1v[i & (HIDn - 1)];
    g_h[i] = fmaxf(v, 0.f);
}

// ---------------------------------------------------------------------------
// GATE (R3/R10 skeleton — fastest measured) with ONE change: the Wl fill
// now uses 16 threads per attribute row loading contiguous float4 runs
// (fully coalesced, 256B per row) instead of a 4B strided gather.
// ---------------------------------------------------------------------------
__global__ void __launch_bounds__(256) gemm_gate(
    const float* __restrict__ W2,  const float* __restrict__ b2v,
    const float* __restrict__ Wl,  const int*   __restrict__ pose)
{
    __shared__ __align__(16) float smemBuf[64 * 68 + 64 * 68];   // 34816 B
    float (*As)[68]   = (float(*)[68]) smemBuf;                  // [16][68]
    float (*Bs)[68]   = (float(*)[68])(smemBuf + 16 * 68);       // [16][68]
    float (*gapT)[68] = (float(*)[68]) smemBuf;                  // [64][68]
    float (*WlT)[68]  = (float(*)[68])(smemBuf + 64 * 68);       // [64][68], [chan][attr]

    int m0 = blockIdx.x * 64;
    int n0 = blockIdx.y * 64;
    int tid = threadIdx.x;
    int tx = tid & 15, ty = tid >> 4;
    int r  = tid >> 2;
    int q  = (tid & 3) * 4;
    float acc[4][4] = {};

    const float* ap = &g_h[(size_t)(m0 + r) * HIDn + q];
    const float* bp = &W2 [(size_t)(n0 + r) * HIDn + q];
    float4 areg = *(const float4*)ap;
    float4 breg = *(const float4*)bp;

    #pragma unroll
    for (int kt = 0; kt < HIDn; kt += 16) {
        As[q+0][r] = areg.x; As[q+1][r] = areg.y; As[q+2][r] = areg.z; As[q+3][r] = areg.w;
        Bs[q+0][r] = breg.x; Bs[q+1][r] = breg.y; Bs[q+2][r] = breg.z; Bs[q+3][r] = breg.w;
        __syncthreads();
        if (kt + 16 < HIDn) {
            areg = *(const float4*)(ap + kt + 16);
            breg = *(const float4*)(bp + kt + 16);
        }
        #pragma unroll
        for (int kk = 0; kk < 16; kk++) {
            float4 a4 = *(const float4*)&As[kk][ty * 4];
            float4 b4 = *(const float4*)&Bs[kk][tx * 4];
            float a[4]  = {a4.x, a4.y, a4.z, a4.w};
            float bb[4] = {b4.x, b4.y, b4.z, b4.w};
            #pragma unroll
            for (int i = 0; i < 4; i++)
                #pragma unroll
                for (int j = 0; j < 4; j++)
                    acc[i][j] = fmaf(a[i], bb[j], acc[i][j]);
        }
        __syncthreads();
    }

    // --- epilogue: gap values -> gapT (chan-major).
    #pragma unroll
    for (int i = 0; i < 4; i++) {
        int m = m0 + ty * 4 + i;
        float fr = (pose[m] == 1) ? 1.0f : 0.0f;
        #pragma unroll
        for (int j = 0; j < 4; j++) {
            int n = n0 + tx * 4 + j;
            float v = acc[i][j] + b2v[n];
            float g = 1.0f / (1.0f + expf(-v));
            gapT[tx * 4 + j][ty * 4 + i] =
                g_bmean[(size_t)m * Cc + n] + fr * g;
        }
    }
    // --- Wl fill, coalesced: 16 threads per attr row j, each loads one
    // float4 from the contiguous 256B run Wl[j][n0..n0+63]; transpose into
    // WlT[chan][attr]. j >= NAT rows are zero-filled.
    #pragma unroll
    for (int jb = 0; jb < 64; jb += 16) {
        int j   = jb + (tid >> 4);          // attr row 0..63
        int cc4 = tid & 15;                 // channel quad 0..15
        float4 v = (j < NAT)
            ? *(const float4*)&Wl[(size_t)j * Cc + n0 + cc4 * 4]
            : make_float4(0.f, 0.f, 0.f, 0.f);
        WlT[cc4 * 4 + 0][j] = v.x;
        WlT[cc4 * 4 + 1][j] = v.y;
        WlT[cc4 * 4 + 2][j] = v.z;
        WlT[cc4 * 4 + 3][j] = v.w;
    }
    __syncthreads();

    // mini-GEMM: zpart[row, attr] = sum_cc gapT[cc][row] * WlT[cc][attr]
    float acc2[4][4] = {};
    #pragma unroll 8
    for (int cc = 0; cc < 64; cc++) {
        float4 g4 = *(const float4*)&gapT[cc][ty * 4];
        float4 w4 = *(const float4*)&WlT [cc][tx * 4];
        float gg[4] = {g4.x, g4.y, g4.z, g4.w};
        float ww[4] = {w4.x, w4.y, w4.z, w4.w};
        #pragma unroll
        for (int i = 0; i < 4; i++)
            #pragma unroll
            for (int j = 0; j < 4; j++)
                acc2[i][j] = fmaf(gg[i], ww[j], acc2[i][j]);
    }
    int nt = blockIdx.y;
    #pragma unroll
    for (int j = 0; j < 4; j++) {
        int attr = tx * 4 + j;
        if (attr < NAT) {
            #pragma unroll
            for (int i = 0; i < 4; i++) {
                int m = m0 + ty * 4 + i;
                g_zp[((size_t)nt * NAT + attr) * Bb + m] = acc2[i][j];
            }
        }
    }
}

// ---------------------------------------------------------------------------
// BN: one block per attribute (NTIL=32 partials).
// ---------------------------------------------------------------------------
__global__ void __launch_bounds__(256) bn_kernel(
    const float* __restrict__ blv, const float* __restrict__ gam,
    const float* __restrict__ bet, float* __restrict__ out)
{
    __shared__ float zbuf[Bb];
    __shared__ float red[256];
    int j   = blockIdx.x;
    int tid = threadIdx.x;
    float bias = blv[j];
    float lsum = 0.f;
    for (int b = tid; b < Bb; b += 256) {
        float z = bias;
        #pragma unroll
        for (int nt = 0; nt < NTIL; nt++)
            z += g_zp[((size_t)nt * NAT + j) * Bb + b];
        zbuf[b] = z;
        lsum += z;
    }
    red[tid] = lsum;
    __syncthreads();
    for (int off = 128; off; off >>= 1) {
        if (tid < off) red[tid] += red[tid + off];
        __syncthreads();
    }
    float mu = red[0] * (1.0f / Bb);
    __syncthreads();
    float lvar = 0.f;
    for (int b = tid; b < Bb; b += 256) {
        float d = zbuf[b] - mu;
        lvar += d * d;
    }
    red[tid] = lvar;
    __syncthreads();
    for (int off = 128; off; off >>= 1) {
        if (tid < off) red[tid] += red[tid + off];
        __syncthreads();
    }
    float inv = rsqrtf(red[0] * (1.0f / Bb) + 1e-5f);
    float ga = gam[j], be = bet[j];
    for (int b = tid; b < Bb; b += 256)
        out[(size_t)b * NAT + j] = ga * (zbuf[b] - mu) * inv + be;
}

// ---------------------------------------------------------------------------
extern "C" void kernel_launch(void* const* d_in, const int* in_sizes, int n_in,
                              void* d_out, int out_size)
{
    const float* body = (const float*)d_in[0];
    const float* face = (const float*)d_in[1];
    const int*   pose = (const int*)  d_in[2];
    const float* Af   = (const float*)d_in[3];
    const float* W1   = (const float*)d_in[4];
    const float* b1v  = (const float*)d_in[5];
    const float* W2   = (const float*)d_in[6];
    const float* b2v  = (const float*)d_in[7];
    const float* Wl   = (const float*)d_in[8];
    const float* blv  = (const float*)d_in[9];
    const float* gam  = (const float*)d_in[10];
    const float* bet  = (const float*)d_in[11];
    float* out = (float*)d_out;

    float *pooled_p, *hp_p;
    cudaGetSymbolAddress((void**)&pooled_p, g_pooled);
    cudaGetSymbolAddress((void**)&hp_p,     g_hp);

    // 1) streaming reduce: pooled max + body mean
    k1_reduce<<<(Bb * Cc) / 64, 256>>>(body, face, Af, pose);
    // 2) hp[s] = pooled @ W1^T  (16-way split-K partials)
    gemm1<<<dim3(Bb / 64, HIDn / 64, S1), 256>>>(pooled_p, W1, hp_p);
    // 3) h = relu(sum hp + b1)
    hreduce<<<(Bb * HIDn) / 256, 256>>>(b1v);
    // 4) gate GEMM (R3 config) + fused z-partial epilogue (coalesced Wl fill)
    gemm_gate<<<dim3(Bb / 64, NTIL), 256>>>(W2, b2v, Wl, pose);
    // 5) reduce partials + bias + batchnorm
    bn_kernel<<<NAT, 256>>>(blv, gam, bet, out);
}

// round 13
// speedup vs baseline: 1.1046x; 1.0148x over previous
#include <cuda_runtime.h>
#include <math.h>
#include <float.h>

#define Bb   512
#define Cc   2048
#define HWn  48
#define NAT  51
#define HIDn 128
#define S1   16    // K-splits for pooled @ W1^T  (K=2048 -> 128/split)
#define NTIL 32    // channel tiles in gate kernel (2048/64)

// Scratch (static __device__ globals: allocation-free rule)
__device__ float g_pooled[Bb * Cc];            // max_hw(body*A*face), 0 for non-front rows
__device__ float g_bmean [Bb * Cc];            // mean_hw(body)
__device__ float g_hp    [S1 * Bb * HIDn];     // split-K partials of pooled @ W1^T
__device__ float g_h     [Bb * HIDn];          // relu(sum hp + b1)
__device__ float g_zp    [NTIL * NAT * Bb];    // per-n-tile partials of gap @ Wl^T, [nt][j][b]

// ---------------------------------------------------------------------------
// K1: streaming pass, float4 loads (R5/R10 version — proven, near HBM bound).
// ---------------------------------------------------------------------------
__global__ void __launch_bounds__(256) k1_reduce(
    const float* __restrict__ body, const float* __restrict__ face,
    const float* __restrict__ Af,   const int*   __restrict__ pose)
{
    __shared__ float sm_s[8][96];
    __shared__ float sm_m[8][96];
    __shared__ float out_s[64], out_m[64];
    int tid  = threadIdx.x;
    int wid  = tid >> 5;
    int lane = tid & 31;
    int blk_ch = blockIdx.x * 64;
    int b = blk_ch >> 11;
    bool front = (pose[b] == 1);
    int wbase = blk_ch + wid * 8;

    const float4* bp4 = (const float4*)body + (size_t)wbase * 12;
    float4 bv[3];
    #pragma unroll
    for (int k = 0; k < 3; k++)
        bv[k] = bp4[k * 32 + lane];
    if (front) {
        const float4* fp4 = (const float4*)face + (size_t)wbase * 12;
        const float4* ap4 = (const float4*)Af   + (size_t)(wbase & (Cc - 1)) * 12;
        #pragma unroll
        for (int k = 0; k < 3; k++) {
            float4 fv = fp4[k * 32 + lane];
            float4 av = ap4[k * 32 + lane];
            float m01 = fmaxf(bv[k].x * av.x * fv.x, bv[k].y * av.y * fv.y);
            float m23 = fmaxf(bv[k].z * av.z * fv.z, bv[k].w * av.w * fv.w);
            sm_m[wid][k * 32 + lane] = fmaxf(m01, m23);
        }
    }
    #pragma unroll
    for (int k = 0; k < 3; k++)
        sm_s[wid][k * 32 + lane] = (bv[k].x + bv[k].y) + (bv[k].z + bv[k].w);
    __syncthreads();

    {
        int chl = tid >> 2;
        int w2  = chl >> 3;
        int off = (chl & 7) * 12 + (tid & 3) * 3;
        float ss = sm_s[w2][off] + sm_s[w2][off + 1] + sm_s[w2][off + 2];
        ss += __shfl_xor_sync(0xffffffffu, ss, 1);
        ss += __shfl_xor_sync(0xffffffffu, ss, 2);
        float mm = 0.f;
        if (front) {
            mm = fmaxf(fmaxf(sm_m[w2][off], sm_m[w2][off + 1]), sm_m[w2][off + 2]);
            mm = fmaxf(mm, __shfl_xor_sync(0xffffffffu, mm, 1));
            mm = fmaxf(mm, __shfl_xor_sync(0xffffffffu, mm, 2));
        }
        if ((tid & 3) == 0) {
            out_s[chl] = ss * (1.0f / 48.0f);
            out_m[chl] = mm;
        }
    }
    __syncthreads();
    if (tid < 64)        g_bmean [blk_ch + tid]      = out_s[tid];
    else if (tid < 128)  g_pooled[blk_ch + tid - 64] = out_m[tid - 64];
}

// ---------------------------------------------------------------------------
// GEMM1 split-K: hp[s] = pooled[512, k-chunk] @ W1[128, k-chunk]^T (unchanged)
// ---------------------------------------------------------------------------
__global__ void __launch_bounds__(256) gemm1(
    const float* __restrict__ A, const float* __restrict__ Bw,
    float* __restrict__ hp)
{
    __shared__ float As[16][68];
    __shared__ float Bs[16][68];
    int s  = blockIdx.z;
    int m0 = blockIdx.x * 64;
    int n0 = blockIdx.y * 64;
    int k0 = s * (Cc / S1);
    int tid = threadIdx.x;
    int tx = tid & 15, ty = tid >> 4;
    int r  = tid >> 2;
    int q  = (tid & 3) * 4;
    float acc[4][4] = {};

    const float* ap = &A [(size_t)(m0 + r) * Cc + k0 + q];
    const float* bp = &Bw[(size_t)(n0 + r) * Cc + k0 + q];
    float4 areg = *(const float4*)ap;
    float4 breg = *(const float4*)bp;

    #pragma unroll
    for (int kt = 0; kt < Cc / S1; kt += 16) {
        As[q+0][r] = areg.x; As[q+1][r] = areg.y; As[q+2][r] = areg.z; As[q+3][r] = areg.w;
        Bs[q+0][r] = breg.x; Bs[q+1][r] = breg.y; Bs[q+2][r] = breg.z; Bs[q+3][r] = breg.w;
        __syncthreads();
        if (kt + 16 < Cc / S1) {
            areg = *(const float4*)(ap + kt + 16);
            breg = *(const float4*)(bp + kt + 16);
        }
        #pragma unroll
        for (int kk = 0; kk < 16; kk++) {
            float4 a4 = *(const float4*)&As[kk][ty * 4];
            float4 b4 = *(const float4*)&Bs[kk][tx * 4];
            float a[4]  = {a4.x, a4.y, a4.z, a4.w};
            float bb[4] = {b4.x, b4.y, b4.z, b4.w};
            #pragma unroll
            for (int i = 0; i < 4; i++)
                #pragma unroll
                for (int j = 0; j < 4; j++)
                    acc[i][j] = fmaf(a[i], bb[j], acc[i][j]);
        }
        __syncthreads();
    }
    #pragma unroll
    for (int i = 0; i < 4; i++) {
        int m = m0 + ty * 4 + i;
        #pragma unroll
        for (int j = 0; j < 4; j++) {
            int n = n0 + tx * 4 + j;
            hp[((size_t)s * Bb + m) * HIDn + n] = acc[i][j];
        }
    }
}

// ---------------------------------------------------------------------------
// hreduce: 256 blocks, scalar per thread (proven).
// ---------------------------------------------------------------------------
__global__ void __launch_bounds__(256) hreduce(const float* __restrict__ b1v)
{
    int i = blockIdx.x * 256 + threadIdx.x;
    float v = g_hp[i];
    #pragma unroll
    for (int s = 1; s < S1; s++)
        v += g_hp[(size_t)s * (Bb * HIDn) + i];
    v += b1v[i & (HIDn - 1)];
    g_h[i] = fmaxf(v, 0.f);
}

// ---------------------------------------------------------------------------
// GATE (R12 skeleton) with ONE change: all epilogue operands (bmean tile,
// Wl tile, pose flags) are PREFETCHED into registers before the mainloop,
// so their memory latency overlaps the 8 k-tile FFMA loop instead of being
// exposed after it.
// ---------------------------------------------------------------------------
__global__ void __launch_bounds__(256) gemm_gate(
    const float* __restrict__ W2,  const float* __restrict__ b2v,
    const float* __restrict__ Wl,  const int*   __restrict__ pose)
{
    __shared__ __align__(16) float smemBuf[64 * 68 + 64 * 68];   // 34816 B
    float (*As)[68]   = (float(*)[68]) smemBuf;                  // [16][68]
    float (*Bs)[68]   = (float(*)[68])(smemBuf + 16 * 68);       // [16][68]
    float (*gapT)[68] = (float(*)[68]) smemBuf;                  // [64][68]
    float (*WlT)[68]  = (float(*)[68])(smemBuf + 64 * 68);       // [64][68], [chan][attr]

    int m0 = blockIdx.x * 64;
    int n0 = blockIdx.y * 64;
    int tid = threadIdx.x;
    int tx = tid & 15, ty = tid >> 4;
    int r  = tid >> 2;
    int q  = (tid & 3) * 4;
    float acc[4][4] = {};

    // ---- PREFETCH epilogue operands (independent LDGs, hidden by mainloop)
    float4 bm[4];
    float  fr[4];
    #pragma unroll
    for (int i = 0; i < 4; i++) {
        int m = m0 + ty * 4 + i;
        bm[i] = *(const float4*)&g_bmean[(size_t)m * Cc + n0 + tx * 4];
        fr[i] = (pose[m] == 1) ? 1.0f : 0.0f;
    }
    float4 wlv[4];
    #pragma unroll
    for (int jb = 0; jb < 4; jb++) {
        int j = jb * 16 + (tid >> 4);
        wlv[jb] = (j < NAT)
            ? *(const float4*)&Wl[(size_t)j * Cc + n0 + (tid & 15) * 4]
            : make_float4(0.f, 0.f, 0.f, 0.f);
    }

    const float* ap = &g_h[(size_t)(m0 + r) * HIDn + q];
    const float* bp = &W2 [(size_t)(n0 + r) * HIDn + q];
    float4 areg = *(const float4*)ap;
    float4 breg = *(const float4*)bp;

    #pragma unroll
    for (int kt = 0; kt < HIDn; kt += 16) {
        As[q+0][r] = areg.x; As[q+1][r] = areg.y; As[q+2][r] = areg.z; As[q+3][r] = areg.w;
        Bs[q+0][r] = breg.x; Bs[q+1][r] = breg.y; Bs[q+2][r] = breg.z; Bs[q+3][r] = breg.w;
        __syncthreads();
        if (kt + 16 < HIDn) {
            areg = *(const float4*)(ap + kt + 16);
            breg = *(const float4*)(bp + kt + 16);
        }
        #pragma unroll
        for (int kk = 0; kk < 16; kk++) {
            float4 a4 = *(const float4*)&As[kk][ty * 4];
            float4 b4 = *(const float4*)&Bs[kk][tx * 4];
            float a[4]  = {a4.x, a4.y, a4.z, a4.w};
            float bb[4] = {b4.x, b4.y, b4.z, b4.w};
            #pragma unroll
            for (int i = 0; i < 4; i++)
                #pragma unroll
                for (int j = 0; j < 4; j++)
                    acc[i][j] = fmaf(a[i], bb[j], acc[i][j]);
        }
        __syncthreads();
    }

    // --- epilogue: gap values -> gapT (chan-major), all operands in regs.
    #pragma unroll
    for (int i = 0; i < 4; i++) {
        float bmr[4] = {bm[i].x, bm[i].y, bm[i].z, bm[i].w};
        #pragma unroll
        for (int j = 0; j < 4; j++) {
            int n = n0 + tx * 4 + j;
            float v = acc[i][j] + b2v[n];
            float g = 1.0f / (1.0f + expf(-v));
            gapT[tx * 4 + j][ty * 4 + i] = bmr[j] + fr[i] * g;
        }
    }
    // --- Wl fill from prefetched registers (transpose into WlT[chan][attr]).
    #pragma unroll
    for (int jb = 0; jb < 4; jb++) {
        int j   = jb * 16 + (tid >> 4);
        int cc4 = tid & 15;
        WlT[cc4 * 4 + 0][j] = wlv[jb].x;
        WlT[cc4 * 4 + 1][j] = wlv[jb].y;
        WlT[cc4 * 4 + 2][j] = wlv[jb].z;
        WlT[cc4 * 4 + 3][j] = wlv[jb].w;
    }
    __syncthreads();

    // mini-GEMM: zpart[row, attr] = sum_cc gapT[cc][row] * WlT[cc][attr]
    float acc2[4][4] = {};
    #pragma unroll 8
    for (int cc = 0; cc < 64; cc++) {
        float4 g4 = *(const float4*)&gapT[cc][ty * 4];
        float4 w4 = *(const float4*)&WlT [cc][tx * 4];
        float gg[4] = {g4.x, g4.y, g4.z, g4.w};
        float ww[4] = {w4.x, w4.y, w4.z, w4.w};
        #pragma unroll
        for (int i = 0; i < 4; i++)
            #pragma unroll
            for (int j = 0; j < 4; j++)
                acc2[i][j] = fmaf(gg[i], ww[j], acc2[i][j]);
    }
    int nt = blockIdx.y;
    #pragma unroll
    for (int j = 0; j < 4; j++) {
        int attr = tx * 4 + j;
        if (attr < NAT) {
            #pragma unroll
            for (int i = 0; i < 4; i++) {
                int m = m0 + ty * 4 + i;
                g_zp[((size_t)nt * NAT + attr) * Bb + m] = acc2[i][j];
            }
        }
    }
}

// ---------------------------------------------------------------------------
// BN: one block per attribute (NTIL=32 partials).
// ---------------------------------------------------------------------------
__global__ void __launch_bounds__(256) bn_kernel(
    const float* __restrict__ blv, const float* __restrict__ gam,
    const float* __restrict__ bet, float* __restrict__ out)
{
    __shared__ float zbuf[Bb];
    __shared__ float red[256];
    int j   = blockIdx.x;
    int tid = threadIdx.x;
    float bias = blv[j];
    float lsum = 0.f;
    for (int b = tid; b < Bb; b += 256) {
        float z = bias;
        #pragma unroll
        for (int nt = 0; nt < NTIL; nt++)
            z += g_zp[((size_t)nt * NAT + j) * Bb + b];
        zbuf[b] = z;
        lsum += z;
    }
    red[tid] = lsum;
    __syncthreads();
    for (int off = 128; off; off >>= 1) {
        if (tid < off) red[tid] += red[tid + off];
        __syncthreads();
    }
    float mu = red[0] * (1.0f / Bb);
    __syncthreads();
    float lvar = 0.f;
    for (int b = tid; b < Bb; b += 256) {
        float d = zbuf[b] - mu;
        lvar += d * d;
    }
    red[tid] = lvar;
    __syncthreads();
    for (int off = 128; off; off >>= 1) {
        if (tid < off) red[tid] += red[tid + off];
        __syncthreads();
    }
    float inv = rsqrtf(red[0] * (1.0f / Bb) + 1e-5f);
    float ga = gam[j], be = bet[j];
    for (int b = tid; b < Bb; b += 256)
        out[(size_t)b * NAT + j] = ga * (zbuf[b] - mu) * inv + be;
}

// ---------------------------------------------------------------------------
extern "C" void kernel_launch(void* const* d_in, const int* in_sizes, int n_in,
                              void* d_out, int out_size)
{
    const float* body = (const float*)d_in[0];
    const float* face = (const float*)d_in[1];
    const int*   pose = (const int*)  d_in[2];
    const float* Af   = (const float*)d_in[3];
    const float* W1   = (const float*)d_in[4];
    const float* b1v  = (const float*)d_in[5];
    const float* W2   = (const float*)d_in[6];
    const float* b2v  = (const float*)d_in[7];
    const float* Wl   = (const float*)d_in[8];
    const float* blv  = (const float*)d_in[9];
    const float* gam  = (const float*)d_in[10];
    const float* bet  = (const float*)d_in[11];
    float* out = (float*)d_out;

    float *pooled_p, *hp_p;
    cudaGetSymbolAddress((void**)&pooled_p, g_pooled);
    cudaGetSymbolAddress((void**)&hp_p,     g_hp);

    // 1) streaming reduce: pooled max + body mean
    k1_reduce<<<(Bb * Cc) / 64, 256>>>(body, face, Af, pose);
    // 2) hp[s] = pooled @ W1^T  (16-way split-K partials)
    gemm1<<<dim3(Bb / 64, HIDn / 64, S1), 256>>>(pooled_p, W1, hp_p);
    // 3) h = relu(sum hp + b1)
    hreduce<<<(Bb * HIDn) / 256, 256>>>(b1v);
    // 4) gate GEMM + fused z-partial epilogue (register-prefetched operands)
    gemm_gate<<<dim3(Bb / 64, NTIL), 256>>>(W2, b2v, Wl, pose);
    // 5) reduce partials + bias + batchnorm
    bn_kernel<<<NAT, 256>>>(blv, gam, bet, out);
}

// round 14
// speedup vs baseline: 1.1081x; 1.0032x over previous
#include <cuda_runtime.h>
#include <math.h>
#include <float.h>

#define Bb   512
#define Cc   2048
#define HWn  48
#define NAT  51
#define HIDn 128
#define S1   16    // K-splits for pooled @ W1^T  (K=2048 -> 128/split)
#define NTIL 32    // channel tiles in gate kernel (2048/64)

// Scratch (static __device__ globals: allocation-free rule)
__device__ float g_pooled[Bb * Cc];            // max_hw(body*A*face), 0 for non-front rows
__device__ float g_bmean [Bb * Cc];            // mean_hw(body)
__device__ float g_hp    [S1 * Bb * HIDn];     // split-K partials of pooled @ W1^T
__device__ float g_h     [Bb * HIDn];          // relu(sum hp + b1)
__device__ float g_zp    [NTIL * NAT * Bb];    // per-n-tile partials of gap @ Wl^T, [nt][j][b]

// ---------------------------------------------------------------------------
// K1: streaming pass, float4 loads (proven, near HBM bound). UNCHANGED.
// ---------------------------------------------------------------------------
__global__ void __launch_bounds__(256) k1_reduce(
    const float* __restrict__ body, const float* __restrict__ face,
    const float* __restrict__ Af,   const int*   __restrict__ pose)
{
    __shared__ float sm_s[8][96];
    __shared__ float sm_m[8][96];
    __shared__ float out_s[64], out_m[64];
    int tid  = threadIdx.x;
    int wid  = tid >> 5;
    int lane = tid & 31;
    int blk_ch = blockIdx.x * 64;
    int b = blk_ch >> 11;
    bool front = (pose[b] == 1);
    int wbase = blk_ch + wid * 8;

    const float4* bp4 = (const float4*)body + (size_t)wbase * 12;
    float4 bv[3];
    #pragma unroll
    for (int k = 0; k < 3; k++)
        bv[k] = bp4[k * 32 + lane];
    if (front) {
        const float4* fp4 = (const float4*)face + (size_t)wbase * 12;
        const float4* ap4 = (const float4*)Af   + (size_t)(wbase & (Cc - 1)) * 12;
        #pragma unroll
        for (int k = 0; k < 3; k++) {
            float4 fv = fp4[k * 32 + lane];
            float4 av = ap4[k * 32 + lane];
            float m01 = fmaxf(bv[k].x * av.x * fv.x, bv[k].y * av.y * fv.y);
            float m23 = fmaxf(bv[k].z * av.z * fv.z, bv[k].w * av.w * fv.w);
            sm_m[wid][k * 32 + lane] = fmaxf(m01, m23);
        }
    }
    #pragma unroll
    for (int k = 0; k < 3; k++)
        sm_s[wid][k * 32 + lane] = (bv[k].x + bv[k].y) + (bv[k].z + bv[k].w);
    __syncthreads();

    {
        int chl = tid >> 2;
        int w2  = chl >> 3;
        int off = (chl & 7) * 12 + (tid & 3) * 3;
        float ss = sm_s[w2][off] + sm_s[w2][off + 1] + sm_s[w2][off + 2];
        ss += __shfl_xor_sync(0xffffffffu, ss, 1);
        ss += __shfl_xor_sync(0xffffffffu, ss, 2);
        float mm = 0.f;
        if (front) {
            mm = fmaxf(fmaxf(sm_m[w2][off], sm_m[w2][off + 1]), sm_m[w2][off + 2]);
            mm = fmaxf(mm, __shfl_xor_sync(0xffffffffu, mm, 1));
            mm = fmaxf(mm, __shfl_xor_sync(0xffffffffu, mm, 2));
        }
        if ((tid & 3) == 0) {
            out_s[chl] = ss * (1.0f / 48.0f);
            out_m[chl] = mm;
        }
    }
    __syncthreads();
    if (tid < 64)        g_bmean [blk_ch + tid]      = out_s[tid];
    else if (tid < 128)  g_pooled[blk_ch + tid - 64] = out_m[tid - 64];
}

// ---------------------------------------------------------------------------
// GEMM1 split-K: hp[s] = pooled[512, k-chunk] @ W1[128, k-chunk]^T (unchanged)
// ---------------------------------------------------------------------------
__global__ void __launch_bounds__(256) gemm1(
    const float* __restrict__ A, const float* __restrict__ Bw,
    float* __restrict__ hp)
{
    __shared__ float As[16][68];
    __shared__ float Bs[16][68];
    int s  = blockIdx.z;
    int m0 = blockIdx.x * 64;
    int n0 = blockIdx.y * 64;
    int k0 = s * (Cc / S1);
    int tid = threadIdx.x;
    int tx = tid & 15, ty = tid >> 4;
    int r  = tid >> 2;
    int q  = (tid & 3) * 4;
    float acc[4][4] = {};

    const float* ap = &A [(size_t)(m0 + r) * Cc + k0 + q];
    const float* bp = &Bw[(size_t)(n0 + r) * Cc + k0 + q];
    float4 areg = *(const float4*)ap;
    float4 breg = *(const float4*)bp;

    #pragma unroll
    for (int kt = 0; kt < Cc / S1; kt += 16) {
        As[q+0][r] = areg.x; As[q+1][r] = areg.y; As[q+2][r] = areg.z; As[q+3][r] = areg.w;
        Bs[q+0][r] = breg.x; Bs[q+1][r] = breg.y; Bs[q+2][r] = breg.z; Bs[q+3][r] = breg.w;
        __syncthreads();
        if (kt + 16 < Cc / S1) {
            areg = *(const float4*)(ap + kt + 16);
            breg = *(const float4*)(bp + kt + 16);
        }
        #pragma unroll
        for (int kk = 0; kk < 16; kk++) {
            float4 a4 = *(const float4*)&As[kk][ty * 4];
            float4 b4 = *(const float4*)&Bs[kk][tx * 4];
            float a[4]  = {a4.x, a4.y, a4.z, a4.w};
            float bb[4] = {b4.x, b4.y, b4.z, b4.w};
            #pragma unroll
            for (int i = 0; i < 4; i++)
                #pragma unroll
                for (int j = 0; j < 4; j++)
                    acc[i][j] = fmaf(a[i], bb[j], acc[i][j]);
        }
        __syncthreads();
    }
    #pragma unroll
    for (int i = 0; i < 4; i++) {
        int m = m0 + ty * 4 + i;
        #pragma unroll
        for (int j = 0; j < 4; j++) {
            int n = n0 + tx * 4 + j;
            hp[((size_t)s * Bb + m) * HIDn + n] = acc[i][j];
        }
    }
}

// ---------------------------------------------------------------------------
// hreduce v3: explicit load batching — all 16 split loads issued before any
// arithmetic (tree sum), forcing MLP=16 instead of a serialized add chain.
// ---------------------------------------------------------------------------
__global__ void __launch_bounds__(256) hreduce(const float* __restrict__ b1v)
{
    int i = blockIdx.x * 256 + threadIdx.x;
    float t[S1];
    #pragma unroll
    for (int s = 0; s < S1; s++)
        t[s] = g_hp[(size_t)s * (Bb * HIDn) + i];
    // pairwise tree sum
    #pragma unroll
    for (int st = S1 / 2; st > 0; st >>= 1)
        #pragma unroll
        for (int s = 0; s < st; s++)
            t[s] += t[s + st];
    g_h[i] = fmaxf(t[0] + b1v[i & (HIDn - 1)], 0.f);
}

// ---------------------------------------------------------------------------
// GATE (R13 version — proven, 21.4us). UNCHANGED.
// ---------------------------------------------------------------------------
__global__ void __launch_bounds__(256) gemm_gate(
    const float* __restrict__ W2,  const float* __restrict__ b2v,
    const float* __restrict__ Wl,  const int*   __restrict__ pose)
{
    __shared__ __align__(16) float smemBuf[64 * 68 + 64 * 68];   // 34816 B
    float (*As)[68]   = (float(*)[68]) smemBuf;                  // [16][68]
    float (*Bs)[68]   = (float(*)[68])(smemBuf + 16 * 68);       // [16][68]
    float (*gapT)[68] = (float(*)[68]) smemBuf;                  // [64][68]
    float (*WlT)[68]  = (float(*)[68])(smemBuf + 64 * 68);       // [64][68], [chan][attr]

    int m0 = blockIdx.x * 64;
    int n0 = blockIdx.y * 64;
    int tid = threadIdx.x;
    int tx = tid & 15, ty = tid >> 4;
    int r  = tid >> 2;
    int q  = (tid & 3) * 4;
    float acc[4][4] = {};

    // prefetch epilogue operands (hidden by mainloop)
    float4 bm[4];
    float  fr[4];
    #pragma unroll
    for (int i = 0; i < 4; i++) {
        int m = m0 + ty * 4 + i;
        bm[i] = *(const float4*)&g_bmean[(size_t)m * Cc + n0 + tx * 4];
        fr[i] = (pose[m] == 1) ? 1.0f : 0.0f;
    }
    float4 wlv[4];
    #pragma unroll
    for (int jb = 0; jb < 4; jb++) {
        int j = jb * 16 + (tid >> 4);
        wlv[jb] = (j < NAT)
            ? *(const float4*)&Wl[(size_t)j * Cc + n0 + (tid & 15) * 4]
            : make_float4(0.f, 0.f, 0.f, 0.f);
    }

    const float* ap = &g_h[(size_t)(m0 + r) * HIDn + q];
    const float* bp = &W2 [(size_t)(n0 + r) * HIDn + q];
    float4 areg = *(const float4*)ap;
    float4 breg = *(const float4*)bp;

    #pragma unroll
    for (int kt = 0; kt < HIDn; kt += 16) {
        As[q+0][r] = areg.x; As[q+1][r] = areg.y; As[q+2][r] = areg.z; As[q+3][r] = areg.w;
        Bs[q+0][r] = breg.x; Bs[q+1][r] = breg.y; Bs[q+2][r] = breg.z; Bs[q+3][r] = breg.w;
        __syncthreads();
        if (kt + 16 < HIDn) {
            areg = *(const float4*)(ap + kt + 16);
            breg = *(const float4*)(bp + kt + 16);
        }
        #pragma unroll
        for (int kk = 0; kk < 16; kk++) {
            float4 a4 = *(const float4*)&As[kk][ty * 4];
            float4 b4 = *(const float4*)&Bs[kk][tx * 4];
            float a[4]  = {a4.x, a4.y, a4.z, a4.w};
            float bb[4] = {b4.x, b4.y, b4.z, b4.w};
            #pragma unroll
            for (int i = 0; i < 4; i++)
                #pragma unroll
                for (int j = 0; j < 4; j++)
                    acc[i][j] = fmaf(a[i], bb[j], acc[i][j]);
        }
        __syncthreads();
    }

    #pragma unroll
    for (int i = 0; i < 4; i++) {
        float bmr[4] = {bm[i].x, bm[i].y, bm[i].z, bm[i].w};
        #pragma unroll
        for (int j = 0; j < 4; j++) {
            int n = n0 + tx * 4 + j;
            float v = acc[i][j] + b2v[n];
            float g = 1.0f / (1.0f + expf(-v));
            gapT[tx * 4 + j][ty * 4 + i] = bmr[j] + fr[i] * g;
        }
    }
    #pragma unroll
    for (int jb = 0; jb < 4; jb++) {
        int j   = jb * 16 + (tid >> 4);
        int cc4 = tid & 15;
        WlT[cc4 * 4 + 0][j] = wlv[jb].x;
        WlT[cc4 * 4 + 1][j] = wlv[jb].y;
        WlT[cc4 * 4 + 2][j] = wlv[jb].z;
        WlT[cc4 * 4 + 3][j] = wlv[jb].w;
    }
    __syncthreads();

    float acc2[4][4] = {};
    #pragma unroll 8
    for (int cc = 0; cc < 64; cc++) {
        float4 g4 = *(const float4*)&gapT[cc][ty * 4];
        float4 w4 = *(const float4*)&WlT [cc][tx * 4];
        float gg[4] = {g4.x, g4.y, g4.z, g4.w};
        float ww[4] = {w4.x, w4.y, w4.z, w4.w};
        #pragma unroll
        for (int i = 0; i < 4; i++)
            #pragma unroll
            for (int j = 0; j < 4; j++)
                acc2[i][j] = fmaf(gg[i], ww[j], acc2[i][j]);
    }
    int nt = blockIdx.y;
    #pragma unroll
    for (int j = 0; j < 4; j++) {
        int attr = tx * 4 + j;
        if (attr < NAT) {
            #pragma unroll
            for (int i = 0; i < 4; i++) {
                int m = m0 + ty * 4 + i;
                g_zp[((size_t)nt * NAT + attr) * Bb + m] = acc2[i][j];
            }
        }
    }
}

// ---------------------------------------------------------------------------
// BN v2: explicit load batching for the 32 partials (tree sum, MLP=32),
// each thread owns exactly 2 batch rows (tid, tid+256).
// ---------------------------------------------------------------------------
__global__ void __launch_bounds__(256) bn_kernel(
    const float* __restrict__ blv, const float* __restrict__ gam,
    const float* __restrict__ bet, float* __restrict__ out)
{
    __shared__ float zbuf[Bb];
    __shared__ float red[256];
    int j   = blockIdx.x;
    int tid = threadIdx.x;
    float bias = blv[j];
    float lsum = 0.f;
    #pragma unroll
    for (int bb = 0; bb < 2; bb++) {
        int b = tid + bb * 256;
        float t[NTIL];
        #pragma unroll
        for (int nt = 0; nt < NTIL; nt++)
            t[nt] = g_zp[((size_t)nt * NAT + j) * Bb + b];
        #pragma unroll
        for (int st = NTIL / 2; st > 0; st >>= 1)
            #pragma unroll
            for (int nt = 0; nt < st; nt++)
                t[nt] += t[nt + st];
        float z = bias + t[0];
        zbuf[b] = z;
        lsum += z;
    }
    red[tid] = lsum;
    __syncthreads();
    for (int off = 128; off; off >>= 1) {
        if (tid < off) red[tid] += red[tid + off];
        __syncthreads();
    }
    float mu = red[0] * (1.0f / Bb);
    __syncthreads();
    float lvar = 0.f;
    #pragma unroll
    for (int bb = 0; bb < 2; bb++) {
        float d = zbuf[tid + bb * 256] - mu;
        lvar += d * d;
    }
    red[tid] = lvar;
    __syncthreads();
    for (int off = 128; off; off >>= 1) {
        if (tid < off) red[tid] += red[tid + off];
        __syncthreads();
    }
    float inv = rsqrtf(red[0] * (1.0f / Bb) + 1e-5f);
    float ga = gam[j], be = bet[j];
    #pragma unroll
    for (int bb = 0; bb < 2; bb++) {
        int b = tid + bb * 256;
        out[(size_t)b * NAT + j] = ga * (zbuf[b] - mu) * inv + be;
    }
}

// ---------------------------------------------------------------------------
extern "C" void kernel_launch(void* const* d_in, const int* in_sizes, int n_in,
                              void* d_out, int out_size)
{
    const float* body = (const float*)d_in[0];
    const float* face = (const float*)d_in[1];
    const int*   pose = (const int*)  d_in[2];
    const float* Af   = (const float*)d_in[3];
    const float* W1   = (const float*)d_in[4];
    const float* b1v  = (const float*)d_in[5];
    const float* W2   = (const float*)d_in[6];
    const float* b2v  = (const float*)d_in[7];
    const float* Wl   = (const float*)d_in[8];
    const float* blv  = (const float*)d_in[9];
    const float* gam  = (const float*)d_in[10];
    const float* bet  = (const float*)d_in[11];
    float* out = (float*)d_out;

    float *pooled_p, *hp_p;
    cudaGetSymbolAddress((void**)&pooled_p, g_pooled);
    cudaGetSymbolAddress((void**)&hp_p,     g_hp);

    // 1) streaming reduce: pooled max + body mean
    k1_reduce<<<(Bb * Cc) / 64, 256>>>(body, face, Af, pose);
    // 2) hp[s] = pooled @ W1^T  (16-way split-K partials)
    gemm1<<<dim3(Bb / 64, HIDn / 64, S1), 256>>>(pooled_p, W1, hp_p);
    // 3) h = relu(sum hp + b1)  (batched loads, MLP=16)
    hreduce<<<(Bb * HIDn) / 256, 256>>>(b1v);
    // 4) gate GEMM + fused z-partial epilogue (register-prefetched operands)
    gemm_gate<<<dim3(Bb / 64, NTIL), 256>>>(W2, b2v, Wl, pose);
    // 5) reduce partials + bias + batchnorm (batched loads, MLP=32)
    bn_kernel<<<NAT, 256>>>(blv, gam, bet, out);
}

// round 15
// speedup vs baseline: 1.1449x; 1.0332x over previous
#include <cuda_runtime.h>
#include <math.h>
#include <float.h>

#define Bb   512
#define Cc   2048
#define HWn  48
#define NAT  51
#define HIDn 128
#define S1   16    // K-splits for pooled @ W1^T  (K=2048 -> 128/split)
#define NTIL 32    // channel tiles in gate kernel (2048/64)

// Scratch (static __device__ globals: allocation-free rule)
__device__ float g_pooled[Bb * Cc];            // max_hw(body*A*face), 0 for non-front rows
__device__ float g_bmean [Bb * Cc];            // mean_hw(body)
__device__ float g_hp    [S1 * Bb * HIDn];     // split-K partials of pooled @ W1^T
__device__ float g_h     [Bb * HIDn];          // relu(sum hp + b1)
__device__ float g_zp    [NTIL * NAT * Bb];    // per-n-tile partials of gap @ Wl^T, [nt][j][b]

// ---------------------------------------------------------------------------
// tf32 helpers
// ---------------------------------------------------------------------------
__device__ __forceinline__ unsigned tf32cvt(float x) {
    unsigned r;
    asm("cvt.rna.tf32.f32 %0, %1;" : "=r"(r) : "f"(x));
    return r;
}
__device__ __forceinline__ void mma_tf32(float c[4],
    unsigned a0, unsigned a1, unsigned a2, unsigned a3,
    unsigned b0, unsigned b1)
{
    asm("mma.sync.aligned.m16n8k8.row.col.f32.tf32.tf32.f32 "
        "{%0,%1,%2,%3}, {%4,%5,%6,%7}, {%8,%9}, {%0,%1,%2,%3};"
        : "+f"(c[0]), "+f"(c[1]), "+f"(c[2]), "+f"(c[3])
        : "r"(a0), "r"(a1), "r"(a2), "r"(a3), "r"(b0), "r"(b1));
}

// ---------------------------------------------------------------------------
// K1: streaming pass, float4 loads (proven, near HBM bound). UNCHANGED.
// ---------------------------------------------------------------------------
__global__ void __launch_bounds__(256) k1_reduce(
    const float* __restrict__ body, const float* __restrict__ face,
    const float* __restrict__ Af,   const int*   __restrict__ pose)
{
    __shared__ float sm_s[8][96];
    __shared__ float sm_m[8][96];
    __shared__ float out_s[64], out_m[64];
    int tid  = threadIdx.x;
    int wid  = tid >> 5;
    int lane = tid & 31;
    int blk_ch = blockIdx.x * 64;
    int b = blk_ch >> 11;
    bool front = (pose[b] == 1);
    int wbase = blk_ch + wid * 8;

    const float4* bp4 = (const float4*)body + (size_t)wbase * 12;
    float4 bv[3];
    #pragma unroll
    for (int k = 0; k < 3; k++)
        bv[k] = bp4[k * 32 + lane];
    if (front) {
        const float4* fp4 = (const float4*)face + (size_t)wbase * 12;
        const float4* ap4 = (const float4*)Af   + (size_t)(wbase & (Cc - 1)) * 12;
        #pragma unroll
        for (int k = 0; k < 3; k++) {
            float4 fv = fp4[k * 32 + lane];
            float4 av = ap4[k * 32 + lane];
            float m01 = fmaxf(bv[k].x * av.x * fv.x, bv[k].y * av.y * fv.y);
            float m23 = fmaxf(bv[k].z * av.z * fv.z, bv[k].w * av.w * fv.w);
            sm_m[wid][k * 32 + lane] = fmaxf(m01, m23);
        }
    }
    #pragma unroll
    for (int k = 0; k < 3; k++)
        sm_s[wid][k * 32 + lane] = (bv[k].x + bv[k].y) + (bv[k].z + bv[k].w);
    __syncthreads();

    {
        int chl = tid >> 2;
        int w2  = chl >> 3;
        int off = (chl & 7) * 12 + (tid & 3) * 3;
        float ss = sm_s[w2][off] + sm_s[w2][off + 1] + sm_s[w2][off + 2];
        ss += __shfl_xor_sync(0xffffffffu, ss, 1);
        ss += __shfl_xor_sync(0xffffffffu, ss, 2);
        float mm = 0.f;
        if (front) {
            mm = fmaxf(fmaxf(sm_m[w2][off], sm_m[w2][off + 1]), sm_m[w2][off + 2]);
            mm = fmaxf(mm, __shfl_xor_sync(0xffffffffu, mm, 1));
            mm = fmaxf(mm, __shfl_xor_sync(0xffffffffu, mm, 2));
        }
        if ((tid & 3) == 0) {
            out_s[chl] = ss * (1.0f / 48.0f);
            out_m[chl] = mm;
        }
    }
    __syncthreads();
    if (tid < 64)        g_bmean [blk_ch + tid]      = out_s[tid];
    else if (tid < 128)  g_pooled[blk_ch + tid - 64] = out_m[tid - 64];
}

// ---------------------------------------------------------------------------
// GEMM1 split-K (unchanged, fp32 exact)
// ---------------------------------------------------------------------------
__global__ void __launch_bounds__(256) gemm1(
    const float* __restrict__ A, const float* __restrict__ Bw,
    float* __restrict__ hp)
{
    __shared__ float As[16][68];
    __shared__ float Bs[16][68];
    int s  = blockIdx.z;
    int m0 = blockIdx.x * 64;
    int n0 = blockIdx.y * 64;
    int k0 = s * (Cc / S1);
    int tid = threadIdx.x;
    int tx = tid & 15, ty = tid >> 4;
    int r  = tid >> 2;
    int q  = (tid & 3) * 4;
    float acc[4][4] = {};

    const float* ap = &A [(size_t)(m0 + r) * Cc + k0 + q];
    const float* bp = &Bw[(size_t)(n0 + r) * Cc + k0 + q];
    float4 areg = *(const float4*)ap;
    float4 breg = *(const float4*)bp;

    #pragma unroll
    for (int kt = 0; kt < Cc / S1; kt += 16) {
        As[q+0][r] = areg.x; As[q+1][r] = areg.y; As[q+2][r] = areg.z; As[q+3][r] = areg.w;
        Bs[q+0][r] = breg.x; Bs[q+1][r] = breg.y; Bs[q+2][r] = breg.z; Bs[q+3][r] = breg.w;
        __syncthreads();
        if (kt + 16 < Cc / S1) {
            areg = *(const float4*)(ap + kt + 16);
            breg = *(const float4*)(bp + kt + 16);
        }
        #pragma unroll
        for (int kk = 0; kk < 16; kk++) {
            float4 a4 = *(const float4*)&As[kk][ty * 4];
            float4 b4 = *(const float4*)&Bs[kk][tx * 4];
            float a[4]  = {a4.x, a4.y, a4.z, a4.w};
            float bb[4] = {b4.x, b4.y, b4.z, b4.w};
            #pragma unroll
            for (int i = 0; i < 4; i++)
                #pragma unroll
                for (int j = 0; j < 4; j++)
                    acc[i][j] = fmaf(a[i], bb[j], acc[i][j]);
        }
        __syncthreads();
    }
    #pragma unroll
    for (int i = 0; i < 4; i++) {
        int m = m0 + ty * 4 + i;
        #pragma unroll
        for (int j = 0; j < 4; j++) {
            int n = n0 + tx * 4 + j;
            hp[((size_t)s * Bb + m) * HIDn + n] = acc[i][j];
        }
    }
}

// ---------------------------------------------------------------------------
// hreduce: batched loads, tree sum (proven).
// ---------------------------------------------------------------------------
__global__ void __launch_bounds__(256) hreduce(const float* __restrict__ b1v)
{
    int i = blockIdx.x * 256 + threadIdx.x;
    float t[S1];
    #pragma unroll
    for (int s = 0; s < S1; s++)
        t[s] = g_hp[(size_t)s * (Bb * HIDn) + i];
    #pragma unroll
    for (int st = S1 / 2; st > 0; st >>= 1)
        #pragma unroll
        for (int s = 0; s < st; s++)
            t[s] += t[s + st];
    g_h[i] = fmaxf(t[0] + b1v[i & (HIDn - 1)], 0.f);
}

// ---------------------------------------------------------------------------
// GATE v-tf32: same 64x64 tile / staging / epilogue structure, but the
// P = h @ W2^T mainloop runs on tensor cores (mma.m16n8k8.tf32).
// Warp w: m-strip (w&3)*16, n-half (w>>2)*32 (4 subtiles of 8 cols).
// Fragment layout (PTX m16n8k8): gid=lane>>2, tig=lane&3;
//   A: a0(gid,tig) a1(gid+8,tig) a2(gid,tig+4) a3(gid+8,tig+4)
//   B: b0(k=tig,n=gid) b1(k=tig+4,n=gid)
//   C: c0(gid,2tig) c1(gid,2tig+1) c2(gid+8,2tig) c3(gid+8,2tig+1)
// Mini-GEMM epilogue (exact fp32) unchanged — reads gapT, layout-agnostic.
// ---------------------------------------------------------------------------
__global__ void __launch_bounds__(256) gemm_gate(
    const float* __restrict__ W2,  const float* __restrict__ b2v,
    const float* __restrict__ Wl,  const int*   __restrict__ pose)
{
    __shared__ __align__(16) float smemBuf[64 * 68 + 64 * 68];   // 34816 B
    float (*As)[68]   = (float(*)[68]) smemBuf;                  // [16][68]  As[k][m]
    float (*Bs)[68]   = (float(*)[68])(smemBuf + 16 * 68);       // [16][68]  Bs[k][n]
    float (*gapT)[68] = (float(*)[68]) smemBuf;                  // [64][68]
    float (*WlT)[68]  = (float(*)[68])(smemBuf + 64 * 68);       // [64][68]

    int m0 = blockIdx.x * 64;
    int n0 = blockIdx.y * 64;
    int tid = threadIdx.x;
    int tx = tid & 15, ty = tid >> 4;
    int r  = tid >> 2;
    int q  = (tid & 3) * 4;

    int lane = tid & 31;
    int w    = tid >> 5;
    int gid  = lane >> 2;
    int tig  = lane & 3;
    int mbase = (w & 3) * 16;
    int nbase = (w >> 2) * 32;

    float c[4][4] = {};     // [n-subtile][c-reg]

    // ---- prefetch epilogue operands (fragment-indexed), hidden by mainloop
    float  fr2[2];
    float2 bm2[4][2];
    float2 b2p[4];
    #pragma unroll
    for (int i = 0; i < 2; i++) {
        int m = m0 + mbase + gid + i * 8;
        fr2[i] = (pose[m] == 1) ? 1.0f : 0.0f;
        #pragma unroll
        for (int t = 0; t < 4; t++)
            bm2[t][i] = *(const float2*)&g_bmean[(size_t)m * Cc + n0 + nbase + t * 8 + tig * 2];
    }
    #pragma unroll
    for (int t = 0; t < 4; t++)
        b2p[t] = *(const float2*)&b2v[n0 + nbase + t * 8 + tig * 2];
    float4 wlv[4];
    #pragma unroll
    for (int jb = 0; jb < 4; jb++) {
        int j = jb * 16 + (tid >> 4);
        wlv[jb] = (j < NAT)
            ? *(const float4*)&Wl[(size_t)j * Cc + n0 + (tid & 15) * 4]
            : make_float4(0.f, 0.f, 0.f, 0.f);
    }

    const float* ap = &g_h[(size_t)(m0 + r) * HIDn + q];
    const float* bp = &W2 [(size_t)(n0 + r) * HIDn + q];
    float4 areg = *(const float4*)ap;
    float4 breg = *(const float4*)bp;

    #pragma unroll
    for (int kt = 0; kt < HIDn; kt += 16) {
        As[q+0][r] = areg.x; As[q+1][r] = areg.y; As[q+2][r] = areg.z; As[q+3][r] = areg.w;
        Bs[q+0][r] = breg.x; Bs[q+1][r] = breg.y; Bs[q+2][r] = breg.z; Bs[q+3][r] = breg.w;
        __syncthreads();
        if (kt + 16 < HIDn) {
            areg = *(const float4*)(ap + kt + 16);
            breg = *(const float4*)(bp + kt + 16);
        }
        #pragma unroll
        for (int ks = 0; ks < 2; ks++) {
            int kb = ks * 8;
            unsigned A0 = tf32cvt(As[kb + tig    ][mbase + gid    ]);
            unsigned A1 = tf32cvt(As[kb + tig    ][mbase + gid + 8]);
            unsigned A2 = tf32cvt(As[kb + tig + 4][mbase + gid    ]);
            unsigned A3 = tf32cvt(As[kb + tig + 4][mbase + gid + 8]);
            #pragma unroll
            for (int t = 0; t < 4; t++) {
                unsigned B0 = tf32cvt(Bs[kb + tig    ][nbase + t * 8 + gid]);
                unsigned B1 = tf32cvt(Bs[kb + tig + 4][nbase + t * 8 + gid]);
                mma_tf32(c[t], A0, A1, A2, A3, B0, B1);
            }
        }
        __syncthreads();
    }

    // --- epilogue: sigmoid + bmean -> gapT (fragment-indexed writes)
    #pragma unroll
    for (int t = 0; t < 4; t++) {
        float b2x = b2p[t].x, b2y = b2p[t].y;
        #pragma unroll
        for (int i = 0; i < 2; i++) {
            int mrow = mbase + gid + i * 8;
            float vx = c[t][i * 2 + 0] + b2x;
            float vy = c[t][i * 2 + 1] + b2y;
            float gx = 1.0f / (1.0f + expf(-vx));
            float gy = 1.0f / (1.0f + expf(-vy));
            int nl = nbase + t * 8 + tig * 2;
            gapT[nl + 0][mrow] = bm2[t][i].x + fr2[i] * gx;
            gapT[nl + 1][mrow] = bm2[t][i].y + fr2[i] * gy;
        }
    }
    #pragma unroll
    for (int jb = 0; jb < 4; jb++) {
        int j   = jb * 16 + (tid >> 4);
        int cc4 = tid & 15;
        WlT[cc4 * 4 + 0][j] = wlv[jb].x;
        WlT[cc4 * 4 + 1][j] = wlv[jb].y;
        WlT[cc4 * 4 + 2][j] = wlv[jb].z;
        WlT[cc4 * 4 + 3][j] = wlv[jb].w;
    }
    __syncthreads();

    // mini-GEMM (exact fp32): zpart[row, attr] = sum_cc gapT[cc][row]*WlT[cc][attr]
    float acc2[4][4] = {};
    #pragma unroll 8
    for (int cc = 0; cc < 64; cc++) {
        float4 g4 = *(const float4*)&gapT[cc][ty * 4];
        float4 w4 = *(const float4*)&WlT [cc][tx * 4];
        float gg[4] = {g4.x, g4.y, g4.z, g4.w};
        float ww[4] = {w4.x, w4.y, w4.z, w4.w};
        #pragma unroll
        for (int i = 0; i < 4; i++)
            #pragma unroll
            for (int j = 0; j < 4; j++)
                acc2[i][j] = fmaf(gg[i], ww[j], acc2[i][j]);
    }
    int nt = blockIdx.y;
    #pragma unroll
    for (int j = 0; j < 4; j++) {
        int attr = tx * 4 + j;
        if (attr < NAT) {
            #pragma unroll
            for (int i = 0; i < 4; i++) {
                int m = m0 + ty * 4 + i;
                g_zp[((size_t)nt * NAT + attr) * Bb + m] = acc2[i][j];
            }
        }
    }
}

// ---------------------------------------------------------------------------
// BN: batched partial loads + tree sum (proven).
// ---------------------------------------------------------------------------
__global__ void __launch_bounds__(256) bn_kernel(
    const float* __restrict__ blv, const float* __restrict__ gam,
    const float* __restrict__ bet, float* __restrict__ out)
{
    __shared__ float zbuf[Bb];
    __shared__ float red[256];
    int j   = blockIdx.x;
    int tid = threadIdx.x;
    float bias = blv[j];
    float lsum = 0.f;
    #pragma unroll
    for (int bb = 0; bb < 2; bb++) {
        int b = tid + bb * 256;
        float t[NTIL];
        #pragma unroll
        for (int nt = 0; nt < NTIL; nt++)
            t[nt] = g_zp[((size_t)nt * NAT + j) * Bb + b];
        #pragma unroll
        for (int st = NTIL / 2; st > 0; st >>= 1)
            #pragma unroll
            for (int nt = 0; nt < st; nt++)
                t[nt] += t[nt + st];
        float z = bias + t[0];
        zbuf[b] = z;
        lsum += z;
    }
    red[tid] = lsum;
    __syncthreads();
    for (int off = 128; off; off >>= 1) {
        if (tid < off) red[tid] += red[tid + off];
        __syncthreads();
    }
    float mu = red[0] * (1.0f / Bb);
    __syncthreads();
    float lvar = 0.f;
    #pragma unroll
    for (int bb = 0; bb < 2; bb++) {
        float d = zbuf[tid + bb * 256] - mu;
        lvar += d * d;
    }
    red[tid] = lvar;
    __syncthreads();
    for (int off = 128; off; off >>= 1) {
        if (tid < off) red[tid] += red[tid + off];
        __syncthreads();
    }
    float inv = rsqrtf(red[0] * (1.0f / Bb) + 1e-5f);
    float ga = gam[j], be = bet[j];
    #pragma unroll
    for (int bb = 0; bb < 2; bb++) {
        int b = tid + bb * 256;
        out[(size_t)b * NAT + j] = ga * (zbuf[b] - mu) * inv + be;
    }
}

// ---------------------------------------------------------------------------
extern "C" void kernel_launch(void* const* d_in, const int* in_sizes, int n_in,
                              void* d_out, int out_size)
{
    const float* body = (const float*)d_in[0];
    const float* face = (const float*)d_in[1];
    const int*   pose = (const int*)  d_in[2];
    const float* Af   = (const float*)d_in[3];
    const float* W1   = (const float*)d_in[4];
    const float* b1v  = (const float*)d_in[5];
    const float* W2   = (const float*)d_in[6];
    const float* b2v  = (const float*)d_in[7];
    const float* Wl   = (const float*)d_in[8];
    const float* blv  = (const float*)d_in[9];
    const float* gam  = (const float*)d_in[10];
    const float* bet  = (const float*)d_in[11];
    float* out = (float*)d_out;

    float *pooled_p, *hp_p;
    cudaGetSymbolAddress((void**)&pooled_p, g_pooled);
    cudaGetSymbolAddress((void**)&hp_p,     g_hp);

    // 1) streaming reduce: pooled max + body mean
    k1_reduce<<<(Bb * Cc) / 64, 256>>>(body, face, Af, pose);
    // 2) hp[s] = pooled @ W1^T  (16-way split-K partials)
    gemm1<<<dim3(Bb / 64, HIDn / 64, S1), 256>>>(pooled_p, W1, hp_p);
    // 3) h = relu(sum hp + b1)
    hreduce<<<(Bb * HIDn) / 256, 256>>>(b1v);
    // 4) gate GEMM (tf32 tensor-core mainloop) + fused z-partial epilogue
    gemm_gate<<<dim3(Bb / 64, NTIL), 256>>>(W2, b2v, Wl, pose);
    // 5) reduce partials + bias + batchnorm
    bn_kernel<<<NAT, 256>>>(blv, gam, bet, out);
}

// round 16
// speedup vs baseline: 1.2448x; 1.0873x over previous
#include <cuda_runtime.h>
#include <math.h>
#include <float.h>

#define Bb   512
#define Cc   2048
#define HWn  48
#define NAT  51
#define HIDn 128
#define S1   16    // K-splits for pooled @ W1^T  (K=2048 -> 128/split)
#define NTIL 32    // channel tiles in gate kernel (2048/64)

// Scratch (static __device__ globals: allocation-free rule)
__device__ float g_pooled[Bb * Cc];            // max_hw(body*A*face), 0 for non-front rows
__device__ float g_bmean [Bb * Cc];            // mean_hw(body)
__device__ float g_hp    [S1 * Bb * HIDn];     // split-K partials of pooled @ W1^T
__device__ float g_h     [Bb * HIDn];          // relu(sum hp + b1)
__device__ float g_zp    [NTIL * NAT * Bb];    // per-n-tile partials of gap @ Wl^T, [nt][j][b]

// ---------------------------------------------------------------------------
// tf32 helpers
// ---------------------------------------------------------------------------
__device__ __forceinline__ unsigned tf32cvt(float x) {
    unsigned r;
    asm("cvt.rna.tf32.f32 %0, %1;" : "=r"(r) : "f"(x));
    return r;
}
__device__ __forceinline__ float tf32f(float x) {   // tf32 bits stored in a float slot
    return __uint_as_float(tf32cvt(x));
}
__device__ __forceinline__ void mma_tf32(float c[4],
    unsigned a0, unsigned a1, unsigned a2, unsigned a3,
    unsigned b0, unsigned b1)
{
    asm("mma.sync.aligned.m16n8k8.row.col.f32.tf32.tf32.f32 "
        "{%0,%1,%2,%3}, {%4,%5,%6,%7}, {%8,%9}, {%0,%1,%2,%3};"
        : "+f"(c[0]), "+f"(c[1]), "+f"(c[2]), "+f"(c[3])
        : "r"(a0), "r"(a1), "r"(a2), "r"(a3), "r"(b0), "r"(b1));
}

// ---------------------------------------------------------------------------
// K1: streaming pass, float4 loads. ONE change vs R14: __ldcs (evict-first)
// on the single-use body/face streams.
// ---------------------------------------------------------------------------
__global__ void __launch_bounds__(256) k1_reduce(
    const float* __restrict__ body, const float* __restrict__ face,
    const float* __restrict__ Af,   const int*   __restrict__ pose)
{
    __shared__ float sm_s[8][96];
    __shared__ float sm_m[8][96];
    __shared__ float out_s[64], out_m[64];
    int tid  = threadIdx.x;
    int wid  = tid >> 5;
    int lane = tid & 31;
    int blk_ch = blockIdx.x * 64;
    int b = blk_ch >> 11;
    bool front = (pose[b] == 1);
    int wbase = blk_ch + wid * 8;

    const float4* bp4 = (const float4*)body + (size_t)wbase * 12;
    float4 bv[3];
    #pragma unroll
    for (int k = 0; k < 3; k++)
        bv[k] = __ldcs(&bp4[k * 32 + lane]);
    if (front) {
        const float4* fp4 = (const float4*)face + (size_t)wbase * 12;
        const float4* ap4 = (const float4*)Af   + (size_t)(wbase & (Cc - 1)) * 12;
        #pragma unroll
        for (int k = 0; k < 3; k++) {
            float4 fv = __ldcs(&fp4[k * 32 + lane]);
            float4 av = ap4[k * 32 + lane];
            float m01 = fmaxf(bv[k].x * av.x * fv.x, bv[k].y * av.y * fv.y);
            float m23 = fmaxf(bv[k].z * av.z * fv.z, bv[k].w * av.w * fv.w);
            sm_m[wid][k * 32 + lane] = fmaxf(m01, m23);
        }
    }
    #pragma unroll
    for (int k = 0; k < 3; k++)
        sm_s[wid][k * 32 + lane] = (bv[k].x + bv[k].y) + (bv[k].z + bv[k].w);
    __syncthreads();

    {
        int chl = tid >> 2;
        int w2  = chl >> 3;
        int off = (chl & 7) * 12 + (tid & 3) * 3;
        float ss = sm_s[w2][off] + sm_s[w2][off + 1] + sm_s[w2][off + 2];
        ss += __shfl_xor_sync(0xffffffffu, ss, 1);
        ss += __shfl_xor_sync(0xffffffffu, ss, 2);
        float mm = 0.f;
        if (front) {
            mm = fmaxf(fmaxf(sm_m[w2][off], sm_m[w2][off + 1]), sm_m[w2][off + 2]);
            mm = fmaxf(mm, __shfl_xor_sync(0xffffffffu, mm, 1));
            mm = fmaxf(mm, __shfl_xor_sync(0xffffffffu, mm, 2));
        }
        if ((tid & 3) == 0) {
            out_s[chl] = ss * (1.0f / 48.0f);
            out_m[chl] = mm;
        }
    }
    __syncthreads();
    if (tid < 64)        g_bmean [blk_ch + tid]      = out_s[tid];
    else if (tid < 128)  g_pooled[blk_ch + tid - 64] = out_m[tid - 64];
}

// ---------------------------------------------------------------------------
// GEMM1 split-K (unchanged, fp32 exact)
// ---------------------------------------------------------------------------
__global__ void __launch_bounds__(256) gemm1(
    const float* __restrict__ A, const float* __restrict__ Bw,
    float* __restrict__ hp)
{
    __shared__ float As[16][68];
    __shared__ float Bs[16][68];
    int s  = blockIdx.z;
    int m0 = blockIdx.x * 64;
    int n0 = blockIdx.y * 64;
    int k0 = s * (Cc / S1);
    int tid = threadIdx.x;
    int tx = tid & 15, ty = tid >> 4;
    int r  = tid >> 2;
    int q  = (tid & 3) * 4;
    float acc[4][4] = {};

    const float* ap = &A [(size_t)(m0 + r) * Cc + k0 + q];
    const float* bp = &Bw[(size_t)(n0 + r) * Cc + k0 + q];
    float4 areg = *(const float4*)ap;
    float4 breg = *(const float4*)bp;

    #pragma unroll
    for (int kt = 0; kt < Cc / S1; kt += 16) {
        As[q+0][r] = areg.x; As[q+1][r] = areg.y; As[q+2][r] = areg.z; As[q+3][r] = areg.w;
        Bs[q+0][r] = breg.x; Bs[q+1][r] = breg.y; Bs[q+2][r] = breg.z; Bs[q+3][r] = breg.w;
        __syncthreads();
        if (kt + 16 < Cc / S1) {
            areg = *(const float4*)(ap + kt + 16);
            breg = *(const float4*)(bp + kt + 16);
        }
        #pragma unroll
        for (int kk = 0; kk < 16; kk++) {
            float4 a4 = *(const float4*)&As[kk][ty * 4];
            float4 b4 = *(const float4*)&Bs[kk][tx * 4];
            float a[4]  = {a4.x, a4.y, a4.z, a4.w};
            float bb[4] = {b4.x, b4.y, b4.z, b4.w};
            #pragma unroll
            for (int i = 0; i < 4; i++)
                #pragma unroll
                for (int j = 0; j < 4; j++)
                    acc[i][j] = fmaf(a[i], bb[j], acc[i][j]);
        }
        __syncthreads();
    }
    #pragma unroll
    for (int i = 0; i < 4; i++) {
        int m = m0 + ty * 4 + i;
        #pragma unroll
        for (int j = 0; j < 4; j++) {
            int n = n0 + tx * 4 + j;
            hp[((size_t)s * Bb + m) * HIDn + n] = acc[i][j];
        }
    }
}

// ---------------------------------------------------------------------------
// hreduce: batched loads, tree sum (proven).
// ---------------------------------------------------------------------------
__global__ void __launch_bounds__(256) hreduce(const float* __restrict__ b1v)
{
    int i = blockIdx.x * 256 + threadIdx.x;
    float t[S1];
    #pragma unroll
    for (int s = 0; s < S1; s++)
        t[s] = g_hp[(size_t)s * (Bb * HIDn) + i];
    #pragma unroll
    for (int st = S1 / 2; st > 0; st >>= 1)
        #pragma unroll
        for (int s = 0; s < st; s++)
            t[s] += t[s + st];
    g_h[i] = fmaxf(t[0] + b1v[i & (HIDn - 1)], 0.f);
}

// ---------------------------------------------------------------------------
// GATE v-tf32-full: tf32 conversion at STAGING (smem holds tf32 bits),
// and the mini-GEMM epilogue also runs on tensor cores.
// Fragment layout (proven in R15): gid=lane>>2, tig=lane&3;
//   A: a0(m=gid,k=tig) a1(gid+8,tig) a2(gid,tig+4) a3(gid+8,tig+4)
//   B: b0(k=tig,n=gid) b1(k=tig+4,n=gid)
//   C: c0(gid,2tig) c1(gid,2tig+1) c2(gid+8,2tig) c3(gid+8,2tig+1)
// ---------------------------------------------------------------------------
__global__ void __launch_bounds__(256) gemm_gate(
    const float* __restrict__ W2,  const float* __restrict__ b2v,
    const float* __restrict__ Wl,  const int*   __restrict__ pose)
{
    __shared__ __align__(16) float smemBuf[64 * 68 + 64 * 68];   // 34816 B
    float (*As)[68]   = (float(*)[68]) smemBuf;                  // [16][68]  tf32 bits, As[k][m]
    float (*Bs)[68]   = (float(*)[68])(smemBuf + 16 * 68);       // [16][68]  tf32 bits, Bs[k][n]
    float (*gapT)[68] = (float(*)[68]) smemBuf;                  // [64][68]  tf32 bits, [cc][m]
    float (*WlT)[68]  = (float(*)[68])(smemBuf + 64 * 68);       // [64][68]  tf32 bits, [cc][j]

    int m0 = blockIdx.x * 64;
    int n0 = blockIdx.y * 64;
    int tid = threadIdx.x;
    int r  = tid >> 2;
    int q  = (tid & 3) * 4;

    int lane = tid & 31;
    int w    = tid >> 5;
    int gid  = lane >> 2;
    int tig  = lane & 3;
    int mbase = (w & 3) * 16;
    int nbase = (w >> 2) * 32;

    float c[4][4] = {};     // mainloop accum [n-subtile][c-reg]

    // ---- prefetch epilogue operands (fragment-indexed), hidden by mainloop
    float  fr2[2];
    float2 bm2[4][2];
    float2 b2p[4];
    #pragma unroll
    for (int i = 0; i < 2; i++) {
        int m = m0 + mbase + gid + i * 8;
        fr2[i] = (pose[m] == 1) ? 1.0f : 0.0f;
        #pragma unroll
        for (int t = 0; t < 4; t++)
            bm2[t][i] = *(const float2*)&g_bmean[(size_t)m * Cc + n0 + nbase + t * 8 + tig * 2];
    }
    #pragma unroll
    for (int t = 0; t < 4; t++)
        b2p[t] = *(const float2*)&b2v[n0 + nbase + t * 8 + tig * 2];
    float4 wlv[4];
    #pragma unroll
    for (int jb = 0; jb < 4; jb++) {
        int j = jb * 16 + (tid >> 4);
        wlv[jb] = (j < NAT)
            ? *(const float4*)&Wl[(size_t)j * Cc + n0 + (tid & 15) * 4]
            : make_float4(0.f, 0.f, 0.f, 0.f);
    }

    const float* ap = &g_h[(size_t)(m0 + r) * HIDn + q];
    const float* bp = &W2 [(size_t)(n0 + r) * HIDn + q];
    float4 areg = *(const float4*)ap;
    float4 breg = *(const float4*)bp;

    #pragma unroll
    for (int kt = 0; kt < HIDn; kt += 16) {
        // stage with one-time tf32 conversion
        As[q+0][r] = tf32f(areg.x); As[q+1][r] = tf32f(areg.y);
        As[q+2][r] = tf32f(areg.z); As[q+3][r] = tf32f(areg.w);
        Bs[q+0][r] = tf32f(breg.x); Bs[q+1][r] = tf32f(breg.y);
        Bs[q+2][r] = tf32f(breg.z); Bs[q+3][r] = tf32f(breg.w);
        __syncthreads();
        if (kt + 16 < HIDn) {
            areg = *(const float4*)(ap + kt + 16);
            breg = *(const float4*)(bp + kt + 16);
        }
        #pragma unroll
        for (int ks = 0; ks < 2; ks++) {
            int kb = ks * 8;
            unsigned A0 = __float_as_uint(As[kb + tig    ][mbase + gid    ]);
            unsigned A1 = __float_as_uint(As[kb + tig    ][mbase + gid + 8]);
            unsigned A2 = __float_as_uint(As[kb + tig + 4][mbase + gid    ]);
            unsigned A3 = __float_as_uint(As[kb + tig + 4][mbase + gid + 8]);
            #pragma unroll
            for (int t = 0; t < 4; t++) {
                unsigned B0 = __float_as_uint(Bs[kb + tig    ][nbase + t * 8 + gid]);
                unsigned B1 = __float_as_uint(Bs[kb + tig + 4][nbase + t * 8 + gid]);
                mma_tf32(c[t], A0, A1, A2, A3, B0, B1);
            }
        }
        __syncthreads();
    }

    // --- epilogue part 1: sigmoid + bmean -> gapT as tf32 bits
    #pragma unroll
    for (int t = 0; t < 4; t++) {
        float b2x = b2p[t].x, b2y = b2p[t].y;
        #pragma unroll
        for (int i = 0; i < 2; i++) {
            int mrow = mbase + gid + i * 8;
            float vx = c[t][i * 2 + 0] + b2x;
            float vy = c[t][i * 2 + 1] + b2y;
            float gx = 1.0f / (1.0f + expf(-vx));
            float gy = 1.0f / (1.0f + expf(-vy));
            int nl = nbase + t * 8 + tig * 2;
            gapT[nl + 0][mrow] = tf32f(bm2[t][i].x + fr2[i] * gx);
            gapT[nl + 1][mrow] = tf32f(bm2[t][i].y + fr2[i] * gy);
        }
    }
    #pragma unroll
    for (int jb = 0; jb < 4; jb++) {
        int j   = jb * 16 + (tid >> 4);
        int cc4 = tid & 15;
        WlT[cc4 * 4 + 0][j] = tf32f(wlv[jb].x);
        WlT[cc4 * 4 + 1][j] = tf32f(wlv[jb].y);
        WlT[cc4 * 4 + 2][j] = tf32f(wlv[jb].z);
        WlT[cc4 * 4 + 3][j] = tf32f(wlv[jb].w);
    }
    __syncthreads();

    // --- epilogue part 2: mini-GEMM on tensor cores.
    // z[m][j] = sum_cc gap[m][cc] * wl[cc][j]; A = gapT[cc][m], B = WlT[cc][j].
    float zc[4][4] = {};
    #pragma unroll
    for (int kk = 0; kk < 8; kk++) {
        int kb = kk * 8;
        unsigned A0 = __float_as_uint(gapT[kb + tig    ][mbase + gid    ]);
        unsigned A1 = __float_as_uint(gapT[kb + tig    ][mbase + gid + 8]);
        unsigned A2 = __float_as_uint(gapT[kb + tig + 4][mbase + gid    ]);
        unsigned A3 = __float_as_uint(gapT[kb + tig + 4][mbase + gid + 8]);
        #pragma unroll
        for (int t = 0; t < 4; t++) {
            unsigned B0 = __float_as_uint(WlT[kb + tig    ][nbase + t * 8 + gid]);
            unsigned B1 = __float_as_uint(WlT[kb + tig + 4][nbase + t * 8 + gid]);
            mma_tf32(zc[t], A0, A1, A2, A3, B0, B1);
        }
    }
    int nt = blockIdx.y;
    #pragma unroll
    for (int t = 0; t < 4; t++) {
        int attr = nbase + t * 8 + tig * 2;
        int mA = m0 + mbase + gid;
        if (attr < NAT) {
            g_zp[((size_t)nt * NAT + attr) * Bb + mA    ] = zc[t][0];
            g_zp[((size_t)nt * NAT + attr) * Bb + mA + 8] = zc[t][2];
        }
        if (attr + 1 < NAT) {
            g_zp[((size_t)nt * NAT + attr + 1) * Bb + mA    ] = zc[t][1];
            g_zp[((size_t)nt * NAT + attr + 1) * Bb + mA + 8] = zc[t][3];
        }
    }
}

// ---------------------------------------------------------------------------
// BN: batched partial loads + tree sum (proven).
// ---------------------------------------------------------------------------
__global__ void __launch_bounds__(256) bn_kernel(
    const float* __restrict__ blv, const float* __restrict__ gam,
    const float* __restrict__ bet, float* __restrict__ out)
{
    __shared__ float zbuf[Bb];
    __shared__ float red[256];
    int j   = blockIdx.x;
    int tid = threadIdx.x;
    float bias = blv[j];
    float lsum = 0.f;
    #pragma unroll
    for (int bb = 0; bb < 2; bb++) {
        int b = tid + bb * 256;
        float t[NTIL];
        #pragma unroll
        for (int nt = 0; nt < NTIL; nt++)
            t[nt] = g_zp[((size_t)nt * NAT + j) * Bb + b];
        #pragma unroll
        for (int st = NTIL / 2; st > 0; st >>= 1)
            #pragma unroll
            for (int nt = 0; nt < st; nt++)
                t[nt] += t[nt + st];
        float z = bias + t[0];
        zbuf[b] = z;
        lsum += z;
    }
    red[tid] = lsum;
    __syncthreads();
    for (int off = 128; off; off >>= 1) {
        if (tid < off) red[tid] += red[tid + off];
        __syncthreads();
    }
    float mu = red[0] * (1.0f / Bb);
    __syncthreads();
    float lvar = 0.f;
    #pragma unroll
    for (int bb = 0; bb < 2; bb++) {
        float d = zbuf[tid + bb * 256] - mu;
        lvar += d * d;
    }
    red[tid] = lvar;
    __syncthreads();
    for (int off = 128; off; off >>= 1) {
        if (tid < off) red[tid] += red[tid + off];
        __syncthreads();
    }
    float inv = rsqrtf(red[0] * (1.0f / Bb) + 1e-5f);
    float ga = gam[j], be = bet[j];
    #pragma unroll
    for (int bb = 0; bb < 2; bb++) {
        int b = tid + bb * 256;
        out[(size_t)b * NAT + j] = ga * (zbuf[b] - mu) * inv + be;
    }
}

// ---------------------------------------------------------------------------
extern "C" void kernel_launch(void* const* d_in, const int* in_sizes, int n_in,
                              void* d_out, int out_size)
{
    const float* body = (const float*)d_in[0];
    const float* face = (const float*)d_in[1];
    const int*   pose = (const int*)  d_in[2];
    const float* Af   = (const float*)d_in[3];
    const float* W1   = (const float*)d_in[4];
    const float* b1v  = (const float*)d_in[5];
    const float* W2   = (const float*)d_in[6];
    const float* b2v  = (const float*)d_in[7];
    const float* Wl   = (const float*)d_in[8];
    const float* blv  = (const float*)d_in[9];
    const float* gam  = (const float*)d_in[10];
    const float* bet  = (const float*)d_in[11];
    float* out = (float*)d_out;

    float *pooled_p, *hp_p;
    cudaGetSymbolAddress((void**)&pooled_p, g_pooled);
    cudaGetSymbolAddress((void**)&hp_p,     g_hp);

    // 1) streaming reduce: pooled max + body mean (__ldcs streams)
    k1_reduce<<<(Bb * Cc) / 64, 256>>>(body, face, Af, pose);
    // 2) hp[s] = pooled @ W1^T  (16-way split-K partials)
    gemm1<<<dim3(Bb / 64, HIDn / 64, S1), 256>>>(pooled_p, W1, hp_p);
    // 3) h = relu(sum hp + b1)
    hreduce<<<(Bb * HIDn) / 256, 256>>>(b1v);
    // 4) gate GEMM (full tf32: staged-cvt mainloop + MMA epilogue)
    gemm_gate<<<dim3(Bb / 64, NTIL), 256>>>(W2, b2v, Wl, pose);
    // 5) reduce partials + bias + batchnorm
    bn_kernel<<<NAT, 256>>>(blv, gam, bet, out);
}

// round 17
// speedup vs baseline: 1.3159x; 1.0570x over previous
#include <cuda_runtime.h>
#include <math.h>
#include <float.h>

#define Bb   512
#define Cc   2048
#define HWn  48
#define NAT  51
#define HIDn 128
#define S1   16    // K-splits for pooled @ W1^T  (K=2048 -> 128/split)
#define NTIL 32    // channel tiles in gate kernel (2048/64)

// Scratch (static __device__ globals: allocation-free rule)
__device__ float g_pooled[Bb * Cc];            // max_hw(body*A*face), 0 for non-front rows
__device__ float g_bmean [Bb * Cc];            // mean_hw(body)
__device__ float g_hp    [S1 * Bb * HIDn];     // split-K partials of pooled @ W1^T
__device__ float g_h     [Bb * HIDn];          // relu(sum hp + b1)
__device__ float g_zp    [NTIL * NAT * Bb];    // per-n-tile partials of gap @ Wl^T, [nt][j][b]

// ---------------------------------------------------------------------------
// tf32 helpers
// ---------------------------------------------------------------------------
__device__ __forceinline__ unsigned tf32cvt(float x) {
    unsigned r;
    asm("cvt.rna.tf32.f32 %0, %1;" : "=r"(r) : "f"(x));
    return r;
}
__device__ __forceinline__ float tf32f(float x) {   // tf32 bits stored in a float slot
    return __uint_as_float(tf32cvt(x));
}
__device__ __forceinline__ void mma_tf32(float c[4],
    unsigned a0, unsigned a1, unsigned a2, unsigned a3,
    unsigned b0, unsigned b1)
{
    asm("mma.sync.aligned.m16n8k8.row.col.f32.tf32.tf32.f32 "
        "{%0,%1,%2,%3}, {%4,%5,%6,%7}, {%8,%9}, {%0,%1,%2,%3};"
        : "+f"(c[0]), "+f"(c[1]), "+f"(c[2]), "+f"(c[3])
        : "r"(a0), "r"(a1), "r"(a2), "r"(a3), "r"(b0), "r"(b1));
}

// ---------------------------------------------------------------------------
// K1: streaming pass, float4 + __ldcs (proven, near HBM bound). UNCHANGED.
// ---------------------------------------------------------------------------
__global__ void __launch_bounds__(256) k1_reduce(
    const float* __restrict__ body, const float* __restrict__ face,
    const float* __restrict__ Af,   const int*   __restrict__ pose)
{
    __shared__ float sm_s[8][96];
    __shared__ float sm_m[8][96];
    __shared__ float out_s[64], out_m[64];
    int tid  = threadIdx.x;
    int wid  = tid >> 5;
    int lane = tid & 31;
    int blk_ch = blockIdx.x * 64;
    int b = blk_ch >> 11;
    bool front = (pose[b] == 1);
    int wbase = blk_ch + wid * 8;

    const float4* bp4 = (const float4*)body + (size_t)wbase * 12;
    float4 bv[3];
    #pragma unroll
    for (int k = 0; k < 3; k++)
        bv[k] = __ldcs(&bp4[k * 32 + lane]);
    if (front) {
        const float4* fp4 = (const float4*)face + (size_t)wbase * 12;
        const float4* ap4 = (const float4*)Af   + (size_t)(wbase & (Cc - 1)) * 12;
        #pragma unroll
        for (int k = 0; k < 3; k++) {
            float4 fv = __ldcs(&fp4[k * 32 + lane]);
            float4 av = ap4[k * 32 + lane];
            float m01 = fmaxf(bv[k].x * av.x * fv.x, bv[k].y * av.y * fv.y);
            float m23 = fmaxf(bv[k].z * av.z * fv.z, bv[k].w * av.w * fv.w);
            sm_m[wid][k * 32 + lane] = fmaxf(m01, m23);
        }
    }
    #pragma unroll
    for (int k = 0; k < 3; k++)
        sm_s[wid][k * 32 + lane] = (bv[k].x + bv[k].y) + (bv[k].z + bv[k].w);
    __syncthreads();

    {
        int chl = tid >> 2;
        int w2  = chl >> 3;
        int off = (chl & 7) * 12 + (tid & 3) * 3;
        float ss = sm_s[w2][off] + sm_s[w2][off + 1] + sm_s[w2][off + 2];
        ss += __shfl_xor_sync(0xffffffffu, ss, 1);
        ss += __shfl_xor_sync(0xffffffffu, ss, 2);
        float mm = 0.f;
        if (front) {
            mm = fmaxf(fmaxf(sm_m[w2][off], sm_m[w2][off + 1]), sm_m[w2][off + 2]);
            mm = fmaxf(mm, __shfl_xor_sync(0xffffffffu, mm, 1));
            mm = fmaxf(mm, __shfl_xor_sync(0xffffffffu, mm, 2));
        }
        if ((tid & 3) == 0) {
            out_s[chl] = ss * (1.0f / 48.0f);
            out_m[chl] = mm;
        }
    }
    __syncthreads();
    if (tid < 64)        g_bmean [blk_ch + tid]      = out_s[tid];
    else if (tid < 128)  g_pooled[blk_ch + tid - 64] = out_m[tid - 64];
}

// ---------------------------------------------------------------------------
// GEMM1 v-tf32: hp[s] = pooled[512, k-chunk] @ W1[128, k-chunk]^T — the
// PROVEN R16 tf32 mainloop (staged cvt, m16n8k8 fragments), epilogue writes
// c-fragments as float2 pairs into hp.
// ---------------------------------------------------------------------------
__global__ void __launch_bounds__(256) gemm1(
    const float* __restrict__ A, const float* __restrict__ Bw,
    float* __restrict__ hp)
{
    __shared__ __align__(16) float As[16][68];   // tf32 bits, As[k][m]
    __shared__ __align__(16) float Bs[16][68];   // tf32 bits, Bs[k][n]
    int s  = blockIdx.z;
    int m0 = blockIdx.x * 64;
    int n0 = blockIdx.y * 64;
    int k0 = s * (Cc / S1);                      // 128-wide chunk
    int tid = threadIdx.x;
    int r  = tid >> 2;
    int q  = (tid & 3) * 4;

    int lane = tid & 31;
    int w    = tid >> 5;
    int gid  = lane >> 2;
    int tig  = lane & 3;
    int mbase = (w & 3) * 16;
    int nbase = (w >> 2) * 32;

    float c[4][4] = {};

    const float* ap = &A [(size_t)(m0 + r) * Cc + k0 + q];
    const float* bp = &Bw[(size_t)(n0 + r) * Cc + k0 + q];
    float4 areg = *(const float4*)ap;
    float4 breg = *(const float4*)bp;

    #pragma unroll
    for (int kt = 0; kt < Cc / S1; kt += 16) {
        As[q+0][r] = tf32f(areg.x); As[q+1][r] = tf32f(areg.y);
        As[q+2][r] = tf32f(areg.z); As[q+3][r] = tf32f(areg.w);
        Bs[q+0][r] = tf32f(breg.x); Bs[q+1][r] = tf32f(breg.y);
        Bs[q+2][r] = tf32f(breg.z); Bs[q+3][r] = tf32f(breg.w);
        __syncthreads();
        if (kt + 16 < Cc / S1) {
            areg = *(const float4*)(ap + kt + 16);
            breg = *(const float4*)(bp + kt + 16);
        }
        #pragma unroll
        for (int ks = 0; ks < 2; ks++) {
            int kb = ks * 8;
            unsigned A0 = __float_as_uint(As[kb + tig    ][mbase + gid    ]);
            unsigned A1 = __float_as_uint(As[kb + tig    ][mbase + gid + 8]);
            unsigned A2 = __float_as_uint(As[kb + tig + 4][mbase + gid    ]);
            unsigned A3 = __float_as_uint(As[kb + tig + 4][mbase + gid + 8]);
            #pragma unroll
            for (int t = 0; t < 4; t++) {
                unsigned B0 = __float_as_uint(Bs[kb + tig    ][nbase + t * 8 + gid]);
                unsigned B1 = __float_as_uint(Bs[kb + tig + 4][nbase + t * 8 + gid]);
                mma_tf32(c[t], A0, A1, A2, A3, B0, B1);
            }
        }
        __syncthreads();
    }

    // epilogue: fragment rows (gid, gid+8), cols nbase+t*8+tig*2 (+1)
    #pragma unroll
    for (int t = 0; t < 4; t++) {
        int n  = n0 + nbase + t * 8 + tig * 2;
        int mA = m0 + mbase + gid;
        *(float2*)&hp[((size_t)s * Bb + mA    ) * HIDn + n] = make_float2(c[t][0], c[t][1]);
        *(float2*)&hp[((size_t)s * Bb + mA + 8) * HIDn + n] = make_float2(c[t][2], c[t][3]);
    }
}

// ---------------------------------------------------------------------------
// hreduce: batched loads, tree sum (proven).
// ---------------------------------------------------------------------------
__global__ void __launch_bounds__(256) hreduce(const float* __restrict__ b1v)
{
    int i = blockIdx.x * 256 + threadIdx.x;
    float t[S1];
    #pragma unroll
    for (int s = 0; s < S1; s++)
        t[s] = g_hp[(size_t)s * (Bb * HIDn) + i];
    #pragma unroll
    for (int st = S1 / 2; st > 0; st >>= 1)
        #pragma unroll
        for (int s = 0; s < st; s++)
            t[s] += t[s + st];
    g_h[i] = fmaxf(t[0] + b1v[i & (HIDn - 1)], 0.f);
}

// ---------------------------------------------------------------------------
// GATE v-tf32-full (proven R16, 15.0us). UNCHANGED.
// ---------------------------------------------------------------------------
__global__ void __launch_bounds__(256) gemm_gate(
    const float* __restrict__ W2,  const float* __restrict__ b2v,
    const float* __restrict__ Wl,  const int*   __restrict__ pose)
{
    __shared__ __align__(16) float smemBuf[64 * 68 + 64 * 68];   // 34816 B
    float (*As)[68]   = (float(*)[68]) smemBuf;                  // [16][68]  tf32 bits, As[k][m]
    float (*Bs)[68]   = (float(*)[68])(smemBuf + 16 * 68);       // [16][68]  tf32 bits, Bs[k][n]
    float (*gapT)[68] = (float(*)[68]) smemBuf;                  // [64][68]  tf32 bits, [cc][m]
    float (*WlT)[68]  = (float(*)[68])(smemBuf + 64 * 68);       // [64][68]  tf32 bits, [cc][j]

    int m0 = blockIdx.x * 64;
    int n0 = blockIdx.y * 64;
    int tid = threadIdx.x;
    int r  = tid >> 2;
    int q  = (tid & 3) * 4;

    int lane = tid & 31;
    int w    = tid >> 5;
    int gid  = lane >> 2;
    int tig  = lane & 3;
    int mbase = (w & 3) * 16;
    int nbase = (w >> 2) * 32;

    float c[4][4] = {};

    float  fr2[2];
    float2 bm2[4][2];
    float2 b2p[4];
    #pragma unroll
    for (int i = 0; i < 2; i++) {
        int m = m0 + mbase + gid + i * 8;
        fr2[i] = (pose[m] == 1) ? 1.0f : 0.0f;
        #pragma unroll
        for (int t = 0; t < 4; t++)
            bm2[t][i] = *(const float2*)&g_bmean[(size_t)m * Cc + n0 + nbase + t * 8 + tig * 2];
    }
    #pragma unroll
    for (int t = 0; t < 4; t++)
        b2p[t] = *(const float2*)&b2v[n0 + nbase + t * 8 + tig * 2];
    float4 wlv[4];
    #pragma unroll
    for (int jb = 0; jb < 4; jb++) {
        int j = jb * 16 + (tid >> 4);
        wlv[jb] = (j < NAT)
            ? *(const float4*)&Wl[(size_t)j * Cc + n0 + (tid & 15) * 4]
            : make_float4(0.f, 0.f, 0.f, 0.f);
    }

    const float* ap = &g_h[(size_t)(m0 + r) * HIDn + q];
    const float* bp = &W2 [(size_t)(n0 + r) * HIDn + q];
    float4 areg = *(const float4*)ap;
    float4 breg = *(const float4*)bp;

    #pragma unroll
    for (int kt = 0; kt < HIDn; kt += 16) {
        As[q+0][r] = tf32f(areg.x); As[q+1][r] = tf32f(areg.y);
        As[q+2][r] = tf32f(areg.z); As[q+3][r] = tf32f(areg.w);
        Bs[q+0][r] = tf32f(breg.x); Bs[q+1][r] = tf32f(breg.y);
        Bs[q+2][r] = tf32f(breg.z); Bs[q+3][r] = tf32f(breg.w);
        __syncthreads();
        if (kt + 16 < HIDn) {
            areg = *(const float4*)(ap + kt + 16);
            breg = *(const float4*)(bp + kt + 16);
        }
        #pragma unroll
        for (int ks = 0; ks < 2; ks++) {
            int kb = ks * 8;
            unsigned A0 = __float_as_uint(As[kb + tig    ][mbase + gid    ]);
            unsigned A1 = __float_as_uint(As[kb + tig    ][mbase + gid + 8]);
            unsigned A2 = __float_as_uint(As[kb + tig + 4][mbase + gid    ]);
            unsigned A3 = __float_as_uint(As[kb + tig + 4][mbase + gid + 8]);
            #pragma unroll
            for (int t = 0; t < 4; t++) {
                unsigned B0 = __float_as_uint(Bs[kb + tig    ][nbase + t * 8 + gid]);
                unsigned B1 = __float_as_uint(Bs[kb + tig + 4][nbase + t * 8 + gid]);
                mma_tf32(c[t], A0, A1, A2, A3, B0, B1);
            }
        }
        __syncthreads();
    }

    #pragma unroll
    for (int t = 0; t < 4; t++) {
        float b2x = b2p[t].x, b2y = b2p[t].y;
        #pragma unroll
        for (int i = 0; i < 2; i++) {
            int mrow = mbase + gid + i * 8;
            float vx = c[t][i * 2 + 0] + b2x;
            float vy = c[t][i * 2 + 1] + b2y;
            float gx = 1.0f / (1.0f + expf(-vx));
            float gy = 1.0f / (1.0f + expf(-vy));
            int nl = nbase + t * 8 + tig * 2;
            gapT[nl + 0][mrow] = tf32f(bm2[t][i].x + fr2[i] * gx);
            gapT[nl + 1][mrow] = tf32f(bm2[t][i].y + fr2[i] * gy);
        }
    }
    #pragma unroll
    for (int jb = 0; jb < 4; jb++) {
        int j   = jb * 16 + (tid >> 4);
        int cc4 = tid & 15;
        WlT[cc4 * 4 + 0][j] = tf32f(wlv[jb].x);
        WlT[cc4 * 4 + 1][j] = tf32f(wlv[jb].y);
        WlT[cc4 * 4 + 2][j] = tf32f(wlv[jb].z);
        WlT[cc4 * 4 + 3][j] = tf32f(wlv[jb].w);
    }
    __syncthreads();

    float zc[4][4] = {};
    #pragma unroll
    for (int kk = 0; kk < 8; kk++) {
        int kb = kk * 8;
        unsigned A0 = __float_as_uint(gapT[kb + tig    ][mbase + gid    ]);
        unsigned A1 = __float_as_uint(gapT[kb + tig    ][mbase + gid + 8]);
        unsigned A2 = __float_as_uint(gapT[kb + tig + 4][mbase + gid    ]);
        unsigned A3 = __float_as_uint(gapT[kb + tig + 4][mbase + gid + 8]);
        #pragma unroll
        for (int t = 0; t < 4; t++) {
            unsigned B0 = __float_as_uint(WlT[kb + tig    ][nbase + t * 8 + gid]);
            unsigned B1 = __float_as_uint(WlT[kb + tig + 4][nbase + t * 8 + gid]);
            mma_tf32(zc[t], A0, A1, A2, A3, B0, B1);
        }
    }
    int nt = blockIdx.y;
    #pragma unroll
    for (int t = 0; t < 4; t++) {
        int attr = nbase + t * 8 + tig * 2;
        int mA = m0 + mbase + gid;
        if (attr < NAT) {
            g_zp[((size_t)nt * NAT + attr) * Bb + mA    ] = zc[t][0];
            g_zp[((size_t)nt * NAT + attr) * Bb + mA + 8] = zc[t][2];
        }
        if (attr + 1 < NAT) {
            g_zp[((size_t)nt * NAT + attr + 1) * Bb + mA    ] = zc[t][1];
            g_zp[((size_t)nt * NAT + attr + 1) * Bb + mA + 8] = zc[t][3];
        }
    }
}

// ---------------------------------------------------------------------------
// BN: batched partial loads + tree sum (proven).
// ---------------------------------------------------------------------------
__global__ void __launch_bounds__(256) bn_kernel(
    const float* __restrict__ blv, const float* __restrict__ gam,
    const float* __restrict__ bet, float* __restrict__ out)
{
    __shared__ float zbuf[Bb];
    __shared__ float red[256];
    int j   = blockIdx.x;
    int tid = threadIdx.x;
    float bias = blv[j];
    float lsum = 0.f;
    #pragma unroll
    for (int bb = 0; bb < 2; bb++) {
        int b = tid + bb * 256;
        float t[NTIL];
        #pragma unroll
        for (int nt = 0; nt < NTIL; nt++)
            t[nt] = g_zp[((size_t)nt * NAT + j) * Bb + b];
        #pragma unroll
        for (int st = NTIL / 2; st > 0; st >>= 1)
            #pragma unroll
            for (int nt = 0; nt < st; nt++)
                t[nt] += t[nt + st];
        float z = bias + t[0];
        zbuf[b] = z;
        lsum += z;
    }
    red[tid] = lsum;
    __syncthreads();
    for (int off = 128; off; off >>= 1) {
        if (tid < off) red[tid] += red[tid + off];
        __syncthreads();
    }
    float mu = red[0] * (1.0f / Bb);
    __syncthreads();
    float lvar = 0.f;
    #pragma unroll
    for (int bb = 0; bb < 2; bb++) {
        float d = zbuf[tid + bb * 256] - mu;
        lvar += d * d;
    }
    red[tid] = lvar;
    __syncthreads();
    for (int off = 128; off; off >>= 1) {
        if (tid < off) red[tid] += red[tid + off];
        __syncthreads();
    }
    float inv = rsqrtf(red[0] * (1.0f / Bb) + 1e-5f);
    float ga = gam[j], be = bet[j];
    #pragma unroll
    for (int bb = 0; bb < 2; bb++) {
        int b = tid + bb * 256;
        out[(size_t)b * NAT + j] = ga * (zbuf[b] - mu) * inv + be;
    }
}

// ---------------------------------------------------------------------------
extern "C" void kernel_launch(void* const* d_in, const int* in_sizes, int n_in,
                              void* d_out, int out_size)
{
    const float* body = (const float*)d_in[0];
    const float* face = (const float*)d_in[1];
    const int*   pose = (const int*)  d_in[2];
    const float* Af   = (const float*)d_in[3];
    const float* W1   = (const float*)d_in[4];
    const float* b1v  = (const float*)d_in[5];
    const float* W2   = (const float*)d_in[6];
    const float* b2v  = (const float*)d_in[7];
    const float* Wl   = (const float*)d_in[8];
    const float* blv  = (const float*)d_in[9];
    const float* gam  = (const float*)d_in[10];
    const float* bet  = (const float*)d_in[11];
    float* out = (float*)d_out;

    float *pooled_p, *hp_p;
    cudaGetSymbolAddress((void**)&pooled_p, g_pooled);
    cudaGetSymbolAddress((void**)&hp_p,     g_hp);

    // 1) streaming reduce: pooled max + body mean
    k1_reduce<<<(Bb * Cc) / 64, 256>>>(body, face, Af, pose);
    // 2) hp[s] = pooled @ W1^T  (tf32 MMA, 16-way split-K partials)
    gemm1<<<dim3(Bb / 64, HIDn / 64, S1), 256>>>(pooled_p, W1, hp_p);
    // 3) h = relu(sum hp + b1)
    hreduce<<<(Bb * HIDn) / 256, 256>>>(b1v);
    // 4) gate GEMM (full tf32) + fused z-partial epilogue
    gemm_gate<<<dim3(Bb / 64, NTIL), 256>>>(W2, b2v, Wl, pose);
    // 5) reduce partials + bias + batchnorm
    bn_kernel<<<NAT, 256>>>(blv, gam, bet, out);
}